// round 10
// baseline (speedup 1.0000x reference)
#include <cuda_runtime.h>
#include <cuda_fp16.h>
#include <math.h>
#include <stdint.h>

#define N 2048
#define HIDDEN 256
#define HEADS 8
#define DK 32
#define NSPLIT 4
#define KSPAN (N / NSPLIT)
#define NCHUNK (N / 64)
#define BSTR 72   // bias smem row stride in halves (16B-aligned rows: 144B)

// -------------------- scratch (__device__ globals; no allocs allowed) -----
__device__ __half g_bias[N * N];                   // 8 MB fp16 pair bias
__device__ float g_qh[HEADS * N * DK];             // head-major projected q (scaled)
__device__ uint32_t g_kf[HEADS * NCHUNK * 1024];   // fragment-major fp16 K (m16n8k16 B)
__device__ uint32_t g_vf[HEADS * NCHUNK * 1024];   // fragment-major fp16 V (m16n8k16 B)
// split-K partials
__device__ float g_pm[NSPLIT * HEADS * N];
__device__ float g_pl[NSPLIT * HEADS * N];
__device__ float g_pav[NSPLIT * HEADS * N * DK];

// -------------------- helpers ---------------------------------------------
__device__ __forceinline__ uint32_t f2tf(float f) {
    uint32_t u;
    asm("cvt.rna.tf32.f32 %0, %1;" : "=r"(u) : "f"(f));
    return u;
}

__device__ __forceinline__ uint32_t packh2(float lo, float hi) {
    __half2 h = __floats2half2_rn(lo, hi);
    return *reinterpret_cast<uint32_t*>(&h);
}

__device__ __forceinline__ void mma_tf32(float& d0, float& d1, float& d2, float& d3,
                                         uint32_t a0, uint32_t a1, uint32_t a2, uint32_t a3,
                                         uint32_t b0, uint32_t b1)
{
    asm volatile("mma.sync.aligned.m16n8k8.row.col.f32.tf32.tf32.f32 "
                 "{%0,%1,%2,%3}, {%4,%5,%6,%7}, {%8,%9}, {%0,%1,%2,%3};"
                 : "+f"(d0), "+f"(d1), "+f"(d2), "+f"(d3)
                 : "r"(a0), "r"(a1), "r"(a2), "r"(a3), "r"(b0), "r"(b1));
}

__device__ __forceinline__ void mma_f16(float& d0, float& d1, float& d2, float& d3,
                                        uint32_t a0, uint32_t a1, uint32_t a2, uint32_t a3,
                                        uint32_t b0, uint32_t b1)
{
    asm volatile("mma.sync.aligned.m16n8k16.row.col.f32.f16.f16.f32 "
                 "{%0,%1,%2,%3}, {%4,%5,%6,%7}, {%8,%9}, {%0,%1,%2,%3};"
                 : "+f"(d0), "+f"(d1), "+f"(d2), "+f"(d3)
                 : "r"(a0), "r"(a1), "r"(a2), "r"(a3), "r"(b0), "r"(b1));
}

__device__ __forceinline__ void cp16(uint32_t smem_dst, const void* gsrc) {
    asm volatile("cp.async.cg.shared.global [%0], [%1], 16;"
                 :: "r"(smem_dst), "l"(gsrc));
}

// K fragment word index (fp16x2 packed over d-pairs): B-frag of m16n8k16
__device__ __forceinline__ int kaddr16(int key, int d) {
    return ((d >> 4) * 8 + (key >> 3)) * 64 + ((key & 7) * 4 + ((d & 7) >> 1)) * 2 + ((d >> 3) & 1);
}
// V fragment half index (fp16x2 packed over key-pairs)
__device__ __forceinline__ int vaddr16h(int key, int d) {
    return ((((key >> 4) * 4 + (d >> 3)) * 32 + (d & 7) * 4 + ((key & 7) >> 1)) * 2
            + ((key >> 3) & 1)) * 2 + (key & 1);
}

// -------------------- bias kernel (coef MLP collapse inlined, fp16 out) ----
__global__ void bias_kernel(const int* __restrict__ label,
                            const float* __restrict__ dist,
                            const float* __restrict__ contact,
                            const float* __restrict__ Wd1, const float* __restrict__ bd1,
                            const float* __restrict__ Wd2, const float* __restrict__ bd2,
                            const float* __restrict__ Wc1, const float* __restrict__ bc1,
                            const float* __restrict__ Wc2, const float* __restrict__ bc2)
{
    __shared__ float4 cf;
    if (threadIdx.x == 0) {
        float am = 0.f, al = 0.f, c0 = bd2[0] + bc2[0], cm = 0.f;
        #pragma unroll
        for (int h = 0; h < 16; h++) {
            am += Wd1[h]      * Wd2[h];
            al += Wd1[16 + h] * Wd2[h];
            c0 += bd1[h]      * Wd2[h];
            cm += Wc1[h]      * Wc2[h];
            al += Wc1[16 + h] * Wc2[h];
            c0 += bc1[h]      * Wc2[h];
        }
        cf = make_float4(am, cm, al, c0);
    }
    __syncthreads();
    const float am = cf.x, cm = cf.y, al = cf.z, c0 = cf.w;

    int i = blockIdx.x * blockDim.x + threadIdx.x;
    float4 dm = ((const float4*)dist)[i];
    float4 cv = ((const float4*)contact)[i];
    int4   lb = ((const int4*)label)[i];
    float ox = fmaf(am, dm.x, fmaf(cm, cv.x, fmaf(al, (float)lb.x, c0)));
    float oy = fmaf(am, dm.y, fmaf(cm, cv.y, fmaf(al, (float)lb.y, c0)));
    float oz = fmaf(am, dm.z, fmaf(cm, cv.z, fmaf(al, (float)lb.z, c0)));
    float ow = fmaf(am, dm.w, fmaf(cm, cv.w, fmaf(al, (float)lb.w, c0)));
    uint2 r;
    r.x = packh2(ox, oy);
    r.y = packh2(oz, ow);
    ((uint2*)g_bias)[i] = r;
}

// -------------------- tf32 projection GEMM body ----------------------------
// 128 threads, tile 32x64, double-buffered smem. grid.x covers M/32.
// mode 0: head-major scaled (Q)   mode 2: K fp16 fragment-major
// mode 3: V fp16 fragment-major
__device__ __forceinline__ void proj_body(const float* __restrict__ A,
                                          const float* __restrict__ W,
                                          const float* __restrict__ bias,
                                          float* __restrict__ out,
                                          float scale, int mode)
{
    __shared__ uint4 AF[2][8 * 32];    // 8 KB
    __shared__ uint2 BF[2][32 * 32];   // 16 KB

    const int t    = threadIdx.x;      // 0..127
    const int lane = t & 31;
    const int w    = t >> 5;           // 0..3
    const int q    = lane & 3;
    const int g    = lane >> 2;
    const int m0   = blockIdx.x * 32;
    const int n0   = blockIdx.y * 64;
    const int mf    = w >> 1;          // 0..1
    const int nhalf = w & 1;

    float acc[4][4];
    #pragma unroll
    for (int j = 0; j < 4; j++)
        #pragma unroll
        for (int e = 0; e < 4; e++) acc[j][e] = 0.f;

    int a_m[2], a_k4[2], b_k[4], b_n4[4];
    #pragma unroll
    for (int p = 0; p < 2; p++) { int idx = t + p * 128; a_m[p] = idx >> 3; a_k4[p] = idx & 7; }
    #pragma unroll
    for (int p = 0; p < 4; p++) { int idx = t + p * 128; b_k[p] = idx >> 4; b_n4[p] = idx & 15; }

    float4 ra[2], rb[4];
    #pragma unroll
    for (int p = 0; p < 2; p++)
        ra[p] = *(const float4*)&A[(size_t)(m0 + a_m[p]) * 256 + a_k4[p] * 4];
    #pragma unroll
    for (int p = 0; p < 4; p++)
        rb[p] = *(const float4*)&W[(size_t)b_k[p] * 256 + n0 + b_n4[p] * 4];

    for (int c = 0; c < 8; c++) {
        const int buf = c & 1;
        {
            #pragma unroll
            for (int p = 0; p < 2; p++) {
                int m = a_m[p], k4 = a_k4[p];
                float4 v = ra[p];
                int frag = (m >> 4) * 4 + (k4 >> 1);
                int idx  = (k4 & 1) * 2 + ((m & 15) >> 3);
                uint32_t* dst = (uint32_t*)&AF[buf][frag * 32 + ((m & 7) * 4)];
                dst[0 * 4 + idx] = f2tf(v.x);
                dst[1 * 4 + idx] = f2tf(v.y);
                dst[2 * 4 + idx] = f2tf(v.z);
                dst[3 * 4 + idx] = f2tf(v.w);
            }
            #pragma unroll
            for (int p = 0; p < 4; p++) {
                int k = b_k[p], n4 = b_n4[p];
                float4 v = rb[p];
                int frag = (n4 >> 1) * 4 + (k >> 3);
                int hi   = (k >> 2) & 1;
                uint32_t* dst = (uint32_t*)&BF[buf][frag * 32 + (n4 & 1) * 16 + (k & 3)];
                dst[0 * 8 + hi] = f2tf(v.x);
                dst[1 * 8 + hi] = f2tf(v.y);
                dst[2 * 8 + hi] = f2tf(v.z);
                dst[3 * 8 + hi] = f2tf(v.w);
            }
        }
        __syncthreads();

        if (c < 7) {
            int kt = (c + 1) * 32;
            #pragma unroll
            for (int p = 0; p < 2; p++)
                ra[p] = *(const float4*)&A[(size_t)(m0 + a_m[p]) * 256 + kt + a_k4[p] * 4];
            #pragma unroll
            for (int p = 0; p < 4; p++)
                rb[p] = *(const float4*)&W[(size_t)(kt + b_k[p]) * 256 + n0 + b_n4[p] * 4];
        }

        #pragma unroll
        for (int ks = 0; ks < 4; ks++) {
            uint4 a = AF[buf][(mf * 4 + ks) * 32 + lane];
            #pragma unroll
            for (int j = 0; j < 4; j++) {
                uint2 b = BF[buf][((nhalf * 4 + j) * 4 + ks) * 32 + lane];
                mma_tf32(acc[j][0], acc[j][1], acc[j][2], acc[j][3],
                         a.x, a.y, a.z, a.w, b.x, b.y);
            }
        }
    }

    const int row0 = m0 + mf * 16 + g;
    const int key0 = (m0 & 32) + mf * 16 + g;   // key within 64-chunk (modes 2/3)
    const int ck   = m0 >> 6;
    #pragma unroll
    for (int j = 0; j < 4; j++) {
        int col = n0 + nhalf * 32 + j * 8 + 2 * q;
        float2 bz = *(const float2*)&bias[col];
        float v00 = acc[j][0] + bz.x, v01 = acc[j][1] + bz.y;
        float v10 = acc[j][2] + bz.x, v11 = acc[j][3] + bz.y;
        if (mode == 0) {
            v00 *= scale; v01 *= scale; v10 *= scale; v11 *= scale;
            size_t base = (size_t)(col >> 5) * ((size_t)N * 32) + (col & 31);
            *(float2*)&out[base + (size_t)row0 * 32]       = make_float2(v00, v01);
            *(float2*)&out[base + (size_t)(row0 + 8) * 32] = make_float2(v10, v11);
        } else {
            int hh = col >> 5, dd = col & 31;
            if (mode == 2) {
                uint32_t* KD = &g_kf[((size_t)hh * NCHUNK + ck) * 1024];
                KD[kaddr16(key0,     dd)] = packh2(v00, v01);
                KD[kaddr16(key0 + 8, dd)] = packh2(v10, v11);
            } else {
                __half* VD = (__half*)&g_vf[((size_t)hh * NCHUNK + ck) * 1024];
                VD[vaddr16h(key0,     dd)]     = __float2half_rn(v00);
                VD[vaddr16h(key0,     dd + 1)] = __float2half_rn(v01);
                VD[vaddr16h(key0 + 8, dd)]     = __float2half_rn(v10);
                VD[vaddr16h(key0 + 8, dd + 1)] = __float2half_rn(v11);
            }
        }
    }
}

// fused Q/K/V projections: grid (N/32, HIDDEN/64, 3), 128 threads
__global__ __launch_bounds__(128) void qkv_proj(const float* __restrict__ q,
                                                const float* __restrict__ k,
                                                const float* __restrict__ v,
                                                const float* __restrict__ Wq,
                                                const float* __restrict__ Wk,
                                                const float* __restrict__ Wv,
                                                const float* __restrict__ bq,
                                                const float* __restrict__ bk,
                                                const float* __restrict__ bv,
                                                float* __restrict__ oq,
                                                float scale)
{
    int z = blockIdx.z;
    if (z == 0)      proj_body(q, Wq, bq, oq,      scale, 0);
    else if (z == 1) proj_body(k, Wk, bk, nullptr, 1.f,   2);
    else             proj_body(v, Wv, bv, nullptr, 1.f,   3);
}

// -------------------- O-projection with fused split-K combine --------------
// 128 threads, tile 32x64, grid (N/32, HIDDEN/64)
__global__ __launch_bounds__(128) void o_proj_fused(const float* __restrict__ W,
                                                    const float* __restrict__ bo,
                                                    float* __restrict__ out)
{
    __shared__ uint4 AF[2][8 * 32];    // 8 KB
    __shared__ uint2 BF[2][32 * 32];   // 16 KB
    __shared__ float4 WC[32][8];       // 4 KB: [row_local][head] = wgt_s/l

    const int t    = threadIdx.x;
    const int lane = t & 31;
    const int w    = t >> 5;
    const int q    = lane & 3;
    const int g    = lane >> 2;
    const int m0   = blockIdx.x * 32;
    const int n0   = blockIdx.y * 64;
    const int mf    = w >> 1;
    const int nhalf = w & 1;

    // ---- prologue: combine weights for this block's 32 rows x 8 heads ----
    #pragma unroll
    for (int p = 0; p < 2; p++) {
        int idx = t + p * 128;          // 0..255
        int r = idx >> 3, hh = idx & 7;
        int row = m0 + r;
        float pm[4], pl[4];
        float M = -INFINITY;
        #pragma unroll
        for (int s = 0; s < 4; s++) {
            pm[s] = g_pm[(s * HEADS + hh) * N + row];
            pl[s] = g_pl[(s * HEADS + hh) * N + row];
            M = fmaxf(M, pm[s]);
        }
        float wgt[4], l = 0.f;
        #pragma unroll
        for (int s = 0; s < 4; s++) { wgt[s] = __expf(pm[s] - M); l += pl[s] * wgt[s]; }
        float inv = 1.f / l;
        WC[r][hh] = make_float4(wgt[0] * inv, wgt[1] * inv, wgt[2] * inv, wgt[3] * inv);
    }
    __syncthreads();

    float acc[4][4];
    #pragma unroll
    for (int j = 0; j < 4; j++)
        #pragma unroll
        for (int e = 0; e < 4; e++) acc[j][e] = 0.f;

    int a_m[2], a_k4[2], b_k[4], b_n4[4];
    #pragma unroll
    for (int p = 0; p < 2; p++) { int idx = t + p * 128; a_m[p] = idx >> 3; a_k4[p] = idx & 7; }
    #pragma unroll
    for (int p = 0; p < 4; p++) { int idx = t + p * 128; b_k[p] = idx >> 4; b_n4[p] = idx & 15; }

    float4 pv[2][4];
    float4 rb[4];
    #pragma unroll
    for (int p = 0; p < 2; p++) {
        int d0 = a_k4[p] * 4;
        #pragma unroll
        for (int s = 0; s < 4; s++)
            pv[p][s] = *(const float4*)&g_pav[(((size_t)(s * HEADS + 0)) * N + m0 + a_m[p]) * DK + d0];
    }
    #pragma unroll
    for (int p = 0; p < 4; p++)
        rb[p] = *(const float4*)&W[(size_t)b_k[p] * 256 + n0 + b_n4[p] * 4];

    for (int c = 0; c < 8; c++) {
        const int buf = c & 1;
        {
            #pragma unroll
            for (int p = 0; p < 2; p++) {
                int m = a_m[p], k4 = a_k4[p];
                float4 wc = WC[m][c];
                float4 v;
                v.x = wc.x * pv[p][0].x + wc.y * pv[p][1].x + wc.z * pv[p][2].x + wc.w * pv[p][3].x;
                v.y = wc.x * pv[p][0].y + wc.y * pv[p][1].y + wc.z * pv[p][2].y + wc.w * pv[p][3].y;
                v.z = wc.x * pv[p][0].z + wc.y * pv[p][1].z + wc.z * pv[p][2].z + wc.w * pv[p][3].z;
                v.w = wc.x * pv[p][0].w + wc.y * pv[p][1].w + wc.z * pv[p][2].w + wc.w * pv[p][3].w;
                int frag = (m >> 4) * 4 + (k4 >> 1);
                int idx  = (k4 & 1) * 2 + ((m & 15) >> 3);
                uint32_t* dst = (uint32_t*)&AF[buf][frag * 32 + ((m & 7) * 4)];
                dst[0 * 4 + idx] = f2tf(v.x);
                dst[1 * 4 + idx] = f2tf(v.y);
                dst[2 * 4 + idx] = f2tf(v.z);
                dst[3 * 4 + idx] = f2tf(v.w);
            }
            #pragma unroll
            for (int p = 0; p < 4; p++) {
                int k = b_k[p], n4 = b_n4[p];
                float4 v = rb[p];
                int frag = (n4 >> 1) * 4 + (k >> 3);
                int hi   = (k >> 2) & 1;
                uint32_t* dst = (uint32_t*)&BF[buf][frag * 32 + (n4 & 1) * 16 + (k & 3)];
                dst[0 * 8 + hi] = f2tf(v.x);
                dst[1 * 8 + hi] = f2tf(v.y);
                dst[2 * 8 + hi] = f2tf(v.z);
                dst[3 * 8 + hi] = f2tf(v.w);
            }
        }
        __syncthreads();

        if (c < 7) {
            int hh = c + 1;
            #pragma unroll
            for (int p = 0; p < 2; p++) {
                int d0 = a_k4[p] * 4;
                #pragma unroll
                for (int s = 0; s < 4; s++)
                    pv[p][s] = *(const float4*)&g_pav[(((size_t)(s * HEADS + hh)) * N + m0 + a_m[p]) * DK + d0];
            }
            int kt = hh * 32;
            #pragma unroll
            for (int p = 0; p < 4; p++)
                rb[p] = *(const float4*)&W[(size_t)(kt + b_k[p]) * 256 + n0 + b_n4[p] * 4];
        }

        #pragma unroll
        for (int ks = 0; ks < 4; ks++) {
            uint4 a = AF[buf][(mf * 4 + ks) * 32 + lane];
            #pragma unroll
            for (int j = 0; j < 4; j++) {
                uint2 b = BF[buf][((nhalf * 4 + j) * 4 + ks) * 32 + lane];
                mma_tf32(acc[j][0], acc[j][1], acc[j][2], acc[j][3],
                         a.x, a.y, a.z, a.w, b.x, b.y);
            }
        }
    }

    const int row0 = m0 + mf * 16 + g;
    #pragma unroll
    for (int j = 0; j < 4; j++) {
        int col = n0 + nhalf * 32 + j * 8 + 2 * q;
        float2 bz = *(const float2*)&bo[col];
        *(float2*)&out[(size_t)row0 * 256 + col] =
            make_float2(acc[j][0] + bz.x, acc[j][1] + bz.y);
        *(float2*)&out[(size_t)(row0 + 8) * 256 + col] =
            make_float2(acc[j][2] + bz.x, acc[j][3] + bz.y);
    }
}

// -------------------- fp16 tensor-core flash attention ---------------------
// grid (N/64, HEADS, NSPLIT), 128 threads. cp.async double-buffered K/V AND
// fp16 bias tiles (dynamic smem, 34.8 KB).
__global__ __launch_bounds__(128) void attn_mma_kernel()
{
    extern __shared__ uint32_t dsm[];
    uint32_t* KBb = dsm;                     // [2][1024]
    uint32_t* VBb = dsm + 2048;              // [2][1024]
    __half*   BSb = (__half*)(dsm + 4096);   // [2][64*BSTR]

    const int tid  = threadIdx.x;
    const int lane = tid & 31;
    const int warp = tid >> 5;
    const int q    = lane & 3;
    const int g    = lane >> 2;
    const int h  = blockIdx.y;
    const int z  = blockIdx.z;
    const int q0 = blockIdx.x * 64;
    const int wr0 = warp * 16;
    const int row = q0 + wr0 + g;

    uint32_t qa[2][4];
    {
        const float* q0p = &g_qh[((size_t)h * N + row) * DK];
        const float* q8p = q0p + 8 * DK;
        #pragma unroll
        for (int ks = 0; ks < 2; ks++) {
            int d = ks * 16 + 2 * q;
            qa[ks][0] = packh2(q0p[d],     q0p[d + 1]);
            qa[ks][1] = packh2(q8p[d],     q8p[d + 1]);
            qa[ks][2] = packh2(q0p[d + 8], q0p[d + 9]);
            qa[ks][3] = packh2(q8p[d + 8], q8p[d + 9]);
        }
    }

    float o[4][4];
    #pragma unroll
    for (int n = 0; n < 4; n++)
        #pragma unroll
        for (int e = 0; e < 4; e++) o[n][e] = 0.f;

    float m0 = -INFINITY, m8 = -INFINITY, l0 = 0.f, l8 = 0.f;

    const int ck0 = (z * KSPAN) / 64;
    const int nch = KSPAN / 64;

    auto fill = [&](int buf, int ck) {
        const uint4* ks = (const uint4*)&g_kf[(size_t)(h * NCHUNK + ck) * 1024];
        const uint4* vs = (const uint4*)&g_vf[(size_t)(h * NCHUNK + ck) * 1024];
        #pragma unroll
        for (int i = 0; i < 2; i++) {
            int idx = i * 128 + tid;
            cp16((uint32_t)__cvta_generic_to_shared(&KBb[buf * 1024 + idx * 4]), ks + idx);
            cp16((uint32_t)__cvta_generic_to_shared(&VBb[buf * 1024 + idx * 4]), vs + idx);
        }
        const __half* bsrc = &g_bias[(size_t)q0 * N + ck * 64];
        __half* bdst = &BSb[buf * 64 * BSTR];
        #pragma unroll
        for (int i = 0; i < 4; i++) {
            int idx = i * 128 + tid;
            int r = idx >> 3, c8 = idx & 7;
            cp16((uint32_t)__cvta_generic_to_shared(&bdst[r * BSTR + c8 * 8]),
                 &bsrc[(size_t)r * N + c8 * 8]);
        }
    };

    fill(0, ck0);
    asm volatile("cp.async.commit_group;");

    for (int cc = 0; cc < nch; cc++) {
        const int cur = cc & 1;

        if (cc + 1 < nch) {
            fill(1 - cur, ck0 + cc + 1);
            asm volatile("cp.async.commit_group;");
            asm volatile("cp.async.wait_group 1;");
        } else {
            asm volatile("cp.async.wait_group 0;");
        }
        __syncthreads();

        const uint32_t* KBc = &KBb[cur * 1024];
        const uint32_t* VBc = &VBb[cur * 1024];
        const __half*   BSc = &BSb[cur * 64 * BSTR];

        float s[8][4];
        #pragma unroll
        for (int j = 0; j < 8; j++)
            #pragma unroll
            for (int e = 0; e < 4; e++) s[j][e] = 0.f;

        #pragma unroll
        for (int ks = 0; ks < 2; ks++) {
            #pragma unroll
            for (int j = 0; j < 8; j++) {
                uint2 b = *(const uint2*)&KBc[((ks * 8 + j) * 32 + lane) * 2];
                mma_f16(s[j][0], s[j][1], s[j][2], s[j][3],
                        qa[ks][0], qa[ks][1], qa[ks][2], qa[ks][3], b.x, b.y);
            }
        }

        {
            const __half* br0 = &BSc[(wr0 + g) * BSTR];
            const __half* br8 = br0 + 8 * BSTR;
            #pragma unroll
            for (int j = 0; j < 8; j++) {
                float2 b0 = __half22float2(*(const __half2*)&br0[8 * j + 2 * q]);
                float2 b8 = __half22float2(*(const __half2*)&br8[8 * j + 2 * q]);
                s[j][0] += b0.x; s[j][1] += b0.y;
                s[j][2] += b8.x; s[j][3] += b8.y;
            }
        }

        float mx0 = s[0][0], mx8 = s[0][2];
        #pragma unroll
        for (int j = 0; j < 8; j++) {
            mx0 = fmaxf(mx0, fmaxf(s[j][0], s[j][1]));
            mx8 = fmaxf(mx8, fmaxf(s[j][2], s[j][3]));
        }
        mx0 = fmaxf(mx0, __shfl_xor_sync(0xffffffffu, mx0, 1));
        mx0 = fmaxf(mx0, __shfl_xor_sync(0xffffffffu, mx0, 2));
        mx8 = fmaxf(mx8, __shfl_xor_sync(0xffffffffu, mx8, 1));
        mx8 = fmaxf(mx8, __shfl_xor_sync(0xffffffffu, mx8, 2));

        float mn0 = fmaxf(m0, mx0), mn8 = fmaxf(m8, mx8);
        float c0 = __expf(m0 - mn0), c8 = __expf(m8 - mn8);
        m0 = mn0; m8 = mn8;
        l0 *= c0;  l8 *= c8;
        #pragma unroll
        for (int n = 0; n < 4; n++) {
            o[n][0] *= c0; o[n][1] *= c0;
            o[n][2] *= c8; o[n][3] *= c8;
        }

        float p[8][4];
        #pragma unroll
        for (int j = 0; j < 8; j++) {
            p[j][0] = __expf(s[j][0] - m0);
            p[j][1] = __expf(s[j][1] - m0);
            p[j][2] = __expf(s[j][2] - m8);
            p[j][3] = __expf(s[j][3] - m8);
            l0 += p[j][0] + p[j][1];
            l8 += p[j][2] + p[j][3];
        }

        #pragma unroll
        for (int kk = 0; kk < 4; kk++) {
            uint32_t a0 = packh2(p[2 * kk][0],     p[2 * kk][1]);
            uint32_t a1 = packh2(p[2 * kk][2],     p[2 * kk][3]);
            uint32_t a2 = packh2(p[2 * kk + 1][0], p[2 * kk + 1][1]);
            uint32_t a3 = packh2(p[2 * kk + 1][2], p[2 * kk + 1][3]);
            #pragma unroll
            for (int n = 0; n < 4; n++) {
                uint2 b = *(const uint2*)&VBc[((kk * 4 + n) * 32 + lane) * 2];
                mma_f16(o[n][0], o[n][1], o[n][2], o[n][3], a0, a1, a2, a3, b.x, b.y);
            }
        }
        __syncthreads();
    }

    l0 += __shfl_xor_sync(0xffffffffu, l0, 1);
    l0 += __shfl_xor_sync(0xffffffffu, l0, 2);
    l8 += __shfl_xor_sync(0xffffffffu, l8, 1);
    l8 += __shfl_xor_sync(0xffffffffu, l8, 2);

    const int rid = (z * HEADS + h) * N + q0 + wr0 + g;
    if (q == 0) {
        g_pm[rid] = m0;     g_pl[rid] = l0;
        g_pm[rid + 8] = m8; g_pl[rid + 8] = l8;
    }
    float* pav0 = &g_pav[(size_t)rid * DK];
    float* pav8 = &g_pav[(size_t)(rid + 8) * DK];
    #pragma unroll
    for (int n = 0; n < 4; n++) {
        *(float2*)&pav0[8 * n + 2 * q] = make_float2(o[n][0], o[n][1]);
        *(float2*)&pav8[8 * n + 2 * q] = make_float2(o[n][2], o[n][3]);
    }
}

// -------------------- launch ------------------------------------------------
extern "C" void kernel_launch(void* const* d_in, const int* in_sizes, int n_in,
                              void* d_out, int out_size)
{
    const int*   label   = (const int*)  d_in[0];
    const float* dist    = (const float*)d_in[1];
    const float* contact = (const float*)d_in[2];
    const float* q       = (const float*)d_in[3];
    const float* k       = (const float*)d_in[4];
    const float* v       = (const float*)d_in[5];
    const float* Wq = (const float*)d_in[6];  const float* bq = (const float*)d_in[7];
    const float* Wk = (const float*)d_in[8];  const float* bk = (const float*)d_in[9];
    const float* Wv = (const float*)d_in[10]; const float* bv = (const float*)d_in[11];
    const float* Wo = (const float*)d_in[12]; const float* bo = (const float*)d_in[13];
    const float* Wd1 = (const float*)d_in[14]; const float* bd1 = (const float*)d_in[15];
    const float* Wd2 = (const float*)d_in[16]; const float* bd2 = (const float*)d_in[17];
    const float* Wc1 = (const float*)d_in[18]; const float* bc1 = (const float*)d_in[19];
    const float* Wc2 = (const float*)d_in[20]; const float* bc2 = (const float*)d_in[21];
    float* out = (float*)d_out;

    float* p_qh;
    cudaGetSymbolAddress((void**)&p_qh, g_qh);

    bias_kernel<<<(N * N / 4) / 256, 256>>>(label, dist, contact,
                                            Wd1, bd1, Wd2, bd2, Wc1, bc1, Wc2, bc2);

    const float scale = 1.f / sqrtf((float)DK);
    qkv_proj<<<dim3(N / 32, HIDDEN / 64, 3), 128>>>(q, k, v, Wq, Wk, Wv,
                                                    bq, bk, bv, p_qh, scale);

    const int attn_smem = 4096 * 4 + 2 * 64 * BSTR * 2;   // 34816 B
    static int smem_set = 0;
    if (!smem_set) {
        cudaFuncSetAttribute(attn_mma_kernel,
                             cudaFuncAttributeMaxDynamicSharedMemorySize, attn_smem);
        smem_set = 1;
    }
    attn_mma_kernel<<<dim3(N / 64, HEADS, NSPLIT), 128, attn_smem>>>();

    o_proj_fused<<<dim3(N / 32, HIDDEN / 64), 128>>>(Wo, bo, out);
}

// round 11
// speedup vs baseline: 1.1048x; 1.1048x over previous
#include <cuda_runtime.h>
#include <cuda_fp16.h>
#include <math.h>
#include <stdint.h>

#define N 2048
#define HIDDEN 256
#define HEADS 8
#define DK 32
#define NSPLIT 4
#define KSPAN (N / NSPLIT)
#define NCHUNK (N / 64)
#define BSTR 72   // bias smem row stride in halves (16B-aligned rows: 144B)

// -------------------- scratch (__device__ globals; no allocs allowed) -----
__device__ __half g_bias[N * N];                   // 8 MB fp16 pair bias
__device__ float g_qh[HEADS * N * DK];             // head-major projected q (scaled)
__device__ uint32_t g_kf[HEADS * NCHUNK * 1024];   // fragment-major fp16 K (m16n8k16 B)
__device__ uint32_t g_vf[HEADS * NCHUNK * 1024];   // fragment-major fp16 V (m16n8k16 B)
// split-K partials
__device__ float g_pm[NSPLIT * HEADS * N];
__device__ float g_pl[NSPLIT * HEADS * N];
__device__ float g_pav[NSPLIT * HEADS * N * DK];

// -------------------- helpers ---------------------------------------------
__device__ __forceinline__ uint32_t f2tf(float f) {
    uint32_t u;
    asm("cvt.rna.tf32.f32 %0, %1;" : "=r"(u) : "f"(f));
    return u;
}

__device__ __forceinline__ uint32_t packh2(float lo, float hi) {
    __half2 h = __floats2half2_rn(lo, hi);
    return *reinterpret_cast<uint32_t*>(&h);
}

__device__ __forceinline__ void mma_tf32(float& d0, float& d1, float& d2, float& d3,
                                         uint32_t a0, uint32_t a1, uint32_t a2, uint32_t a3,
                                         uint32_t b0, uint32_t b1)
{
    asm volatile("mma.sync.aligned.m16n8k8.row.col.f32.tf32.tf32.f32 "
                 "{%0,%1,%2,%3}, {%4,%5,%6,%7}, {%8,%9}, {%0,%1,%2,%3};"
                 : "+f"(d0), "+f"(d1), "+f"(d2), "+f"(d3)
                 : "r"(a0), "r"(a1), "r"(a2), "r"(a3), "r"(b0), "r"(b1));
}

__device__ __forceinline__ void mma_f16(float& d0, float& d1, float& d2, float& d3,
                                        uint32_t a0, uint32_t a1, uint32_t a2, uint32_t a3,
                                        uint32_t b0, uint32_t b1)
{
    asm volatile("mma.sync.aligned.m16n8k16.row.col.f32.f16.f16.f32 "
                 "{%0,%1,%2,%3}, {%4,%5,%6,%7}, {%8,%9}, {%0,%1,%2,%3};"
                 : "+f"(d0), "+f"(d1), "+f"(d2), "+f"(d3)
                 : "r"(a0), "r"(a1), "r"(a2), "r"(a3), "r"(b0), "r"(b1));
}

__device__ __forceinline__ void cp16(uint32_t smem_dst, const void* gsrc) {
    asm volatile("cp.async.cg.shared.global [%0], [%1], 16;"
                 :: "r"(smem_dst), "l"(gsrc));
}

// K fragment word index (fp16x2 packed over d-pairs): B-frag of m16n8k16
__device__ __forceinline__ int kaddr16(int key, int d) {
    return ((d >> 4) * 8 + (key >> 3)) * 64 + ((key & 7) * 4 + ((d & 7) >> 1)) * 2 + ((d >> 3) & 1);
}
// V fragment half index (fp16x2 packed over key-pairs)
__device__ __forceinline__ int vaddr16h(int key, int d) {
    return ((((key >> 4) * 4 + (d >> 3)) * 32 + (d & 7) * 4 + ((key & 7) >> 1)) * 2
            + ((key >> 3) & 1)) * 2 + (key & 1);
}

// -------------------- bias kernel (coef MLP collapse inlined, fp16 out) ----
__global__ void bias_kernel(const int* __restrict__ label,
                            const float* __restrict__ dist,
                            const float* __restrict__ contact,
                            const float* __restrict__ Wd1, const float* __restrict__ bd1,
                            const float* __restrict__ Wd2, const float* __restrict__ bd2,
                            const float* __restrict__ Wc1, const float* __restrict__ bc1,
                            const float* __restrict__ Wc2, const float* __restrict__ bc2)
{
    __shared__ float4 cf;
    if (threadIdx.x == 0) {
        float am = 0.f, al = 0.f, c0 = bd2[0] + bc2[0], cm = 0.f;
        #pragma unroll
        for (int h = 0; h < 16; h++) {
            am += Wd1[h]      * Wd2[h];
            al += Wd1[16 + h] * Wd2[h];
            c0 += bd1[h]      * Wd2[h];
            cm += Wc1[h]      * Wc2[h];
            al += Wc1[16 + h] * Wc2[h];
            c0 += bc1[h]      * Wc2[h];
        }
        cf = make_float4(am, cm, al, c0);
    }
    __syncthreads();
    const float am = cf.x, cm = cf.y, al = cf.z, c0 = cf.w;

    int i = blockIdx.x * blockDim.x + threadIdx.x;
    float4 dm = ((const float4*)dist)[i];
    float4 cv = ((const float4*)contact)[i];
    int4   lb = ((const int4*)label)[i];
    float ox = fmaf(am, dm.x, fmaf(cm, cv.x, fmaf(al, (float)lb.x, c0)));
    float oy = fmaf(am, dm.y, fmaf(cm, cv.y, fmaf(al, (float)lb.y, c0)));
    float oz = fmaf(am, dm.z, fmaf(cm, cv.z, fmaf(al, (float)lb.z, c0)));
    float ow = fmaf(am, dm.w, fmaf(cm, cv.w, fmaf(al, (float)lb.w, c0)));
    uint2 r;
    r.x = packh2(ox, oy);
    r.y = packh2(oz, ow);
    ((uint2*)g_bias)[i] = r;
}

// -------------------- tf32 projection GEMM body (R9 config: 256thr 64x64) --
// mode 0: head-major scaled (Q)   mode 2: K fp16 fragment-major
// mode 3: V fp16 fragment-major
__device__ __forceinline__ void proj_body(const float* __restrict__ A,
                                          const float* __restrict__ W,
                                          const float* __restrict__ bias,
                                          float* __restrict__ out,
                                          float scale, int mode)
{
    __shared__ uint4 AF[2][16 * 32];   // 16 KB
    __shared__ uint2 BF[2][32 * 32];   // 16 KB

    const int t    = threadIdx.x;
    const int lane = t & 31;
    const int w    = t >> 5;
    const int q    = lane & 3;
    const int g    = lane >> 2;
    const int m0   = blockIdx.x * 64;
    const int n0   = blockIdx.y * 64;
    const int mf    = w >> 1;
    const int nhalf = w & 1;

    float acc[4][4];
    #pragma unroll
    for (int j = 0; j < 4; j++)
        #pragma unroll
        for (int e = 0; e < 4; e++) acc[j][e] = 0.f;

    const int a_m0 = t >> 3,         a_k4_0 = t & 7;
    const int a_m1 = (t + 256) >> 3, a_k4_1 = (t + 256) & 7;
    const int b_k0 = t >> 4,         b_n4_0 = t & 15;
    const int b_k1 = (t + 256) >> 4, b_n4_1 = (t + 256) & 15;

    float4 ra0, ra1, rb0, rb1;
    ra0 = *(const float4*)&A[(size_t)(m0 + a_m0) * 256 + 0 + a_k4_0 * 4];
    ra1 = *(const float4*)&A[(size_t)(m0 + a_m1) * 256 + 0 + a_k4_1 * 4];
    rb0 = *(const float4*)&W[(size_t)(0 + b_k0) * 256 + n0 + b_n4_0 * 4];
    rb1 = *(const float4*)&W[(size_t)(0 + b_k1) * 256 + n0 + b_n4_1 * 4];

    for (int c = 0; c < 8; c++) {
        const int buf = c & 1;
        {
            #pragma unroll
            for (int p = 0; p < 2; p++) {
                int m  = p ? a_m1 : a_m0;
                int k4 = p ? a_k4_1 : a_k4_0;
                float4 v = p ? ra1 : ra0;
                int frag = (m >> 4) * 4 + (k4 >> 1);
                int idx  = (k4 & 1) * 2 + ((m & 15) >> 3);
                uint32_t* dst = (uint32_t*)&AF[buf][frag * 32 + ((m & 7) * 4)];
                dst[0 * 4 + idx] = f2tf(v.x);
                dst[1 * 4 + idx] = f2tf(v.y);
                dst[2 * 4 + idx] = f2tf(v.z);
                dst[3 * 4 + idx] = f2tf(v.w);
            }
            #pragma unroll
            for (int p = 0; p < 2; p++) {
                int k  = p ? b_k1 : b_k0;
                int n4 = p ? b_n4_1 : b_n4_0;
                float4 v = p ? rb1 : rb0;
                int frag = (n4 >> 1) * 4 + (k >> 3);
                int hi   = (k >> 2) & 1;
                uint32_t* dst = (uint32_t*)&BF[buf][frag * 32 + (n4 & 1) * 16 + (k & 3)];
                dst[0 * 8 + hi] = f2tf(v.x);
                dst[1 * 8 + hi] = f2tf(v.y);
                dst[2 * 8 + hi] = f2tf(v.z);
                dst[3 * 8 + hi] = f2tf(v.w);
            }
        }
        __syncthreads();

        if (c < 7) {
            int kt = (c + 1) * 32;
            ra0 = *(const float4*)&A[(size_t)(m0 + a_m0) * 256 + kt + a_k4_0 * 4];
            ra1 = *(const float4*)&A[(size_t)(m0 + a_m1) * 256 + kt + a_k4_1 * 4];
            rb0 = *(const float4*)&W[(size_t)(kt + b_k0) * 256 + n0 + b_n4_0 * 4];
            rb1 = *(const float4*)&W[(size_t)(kt + b_k1) * 256 + n0 + b_n4_1 * 4];
        }

        #pragma unroll
        for (int ks = 0; ks < 4; ks++) {
            uint4 a = AF[buf][(mf * 4 + ks) * 32 + lane];
            #pragma unroll
            for (int j = 0; j < 4; j++) {
                uint2 b = BF[buf][((nhalf * 4 + j) * 4 + ks) * 32 + lane];
                mma_tf32(acc[j][0], acc[j][1], acc[j][2], acc[j][3],
                         a.x, a.y, a.z, a.w, b.x, b.y);
            }
        }
    }

    const int row0 = m0 + mf * 16 + g;
    const int key0 = mf * 16 + g;
    const int ck   = m0 >> 6;
    #pragma unroll
    for (int j = 0; j < 4; j++) {
        int col = n0 + nhalf * 32 + j * 8 + 2 * q;
        float2 bz = *(const float2*)&bias[col];
        float v00 = acc[j][0] + bz.x, v01 = acc[j][1] + bz.y;
        float v10 = acc[j][2] + bz.x, v11 = acc[j][3] + bz.y;
        if (mode == 0) {
            v00 *= scale; v01 *= scale; v10 *= scale; v11 *= scale;
            size_t base = (size_t)(col >> 5) * ((size_t)N * 32) + (col & 31);
            *(float2*)&out[base + (size_t)row0 * 32]       = make_float2(v00, v01);
            *(float2*)&out[base + (size_t)(row0 + 8) * 32] = make_float2(v10, v11);
        } else {
            int hh = col >> 5, dd = col & 31;
            if (mode == 2) {
                uint32_t* KD = &g_kf[((size_t)hh * NCHUNK + ck) * 1024];
                KD[kaddr16(key0,     dd)] = packh2(v00, v01);
                KD[kaddr16(key0 + 8, dd)] = packh2(v10, v11);
            } else {
                __half* VD = (__half*)&g_vf[((size_t)hh * NCHUNK + ck) * 1024];
                VD[vaddr16h(key0,     dd)]     = __float2half_rn(v00);
                VD[vaddr16h(key0,     dd + 1)] = __float2half_rn(v01);
                VD[vaddr16h(key0 + 8, dd)]     = __float2half_rn(v10);
                VD[vaddr16h(key0 + 8, dd + 1)] = __float2half_rn(v11);
            }
        }
    }
}

// fused Q/K/V projections: grid (N/64, HIDDEN/64, 3), 256 threads
__global__ __launch_bounds__(256) void qkv_proj(const float* __restrict__ q,
                                                const float* __restrict__ k,
                                                const float* __restrict__ v,
                                                const float* __restrict__ Wq,
                                                const float* __restrict__ Wk,
                                                const float* __restrict__ Wv,
                                                const float* __restrict__ bq,
                                                const float* __restrict__ bk,
                                                const float* __restrict__ bv,
                                                float* __restrict__ oq,
                                                float scale)
{
    int z = blockIdx.z;
    if (z == 0)      proj_body(q, Wq, bq, oq,      scale, 0);
    else if (z == 1) proj_body(k, Wk, bk, nullptr, 1.f,   2);
    else             proj_body(v, Wv, bv, nullptr, 1.f,   3);
}

// -------------------- O-projection with fused split-K combine (R9) ---------
__global__ __launch_bounds__(256) void o_proj_fused(const float* __restrict__ W,
                                                    const float* __restrict__ bo,
                                                    float* __restrict__ out)
{
    __shared__ uint4 AF[2][16 * 32];   // 16 KB
    __shared__ uint2 BF[2][32 * 32];   // 16 KB
    __shared__ float4 WC[64][8];       // 8 KB

    const int t    = threadIdx.x;
    const int lane = t & 31;
    const int w    = t >> 5;
    const int q    = lane & 3;
    const int g    = lane >> 2;
    const int m0   = blockIdx.x * 64;
    const int n0   = blockIdx.y * 64;
    const int mf    = w >> 1;
    const int nhalf = w & 1;

    #pragma unroll
    for (int p = 0; p < 2; p++) {
        int idx = t + p * 256;
        int r = idx >> 3, hh = idx & 7;
        int row = m0 + r;
        float pm[4], pl[4];
        float M = -INFINITY;
        #pragma unroll
        for (int s = 0; s < 4; s++) {
            pm[s] = g_pm[(s * HEADS + hh) * N + row];
            pl[s] = g_pl[(s * HEADS + hh) * N + row];
            M = fmaxf(M, pm[s]);
        }
        float wgt[4], l = 0.f;
        #pragma unroll
        for (int s = 0; s < 4; s++) { wgt[s] = __expf(pm[s] - M); l += pl[s] * wgt[s]; }
        float inv = 1.f / l;
        WC[r][hh] = make_float4(wgt[0] * inv, wgt[1] * inv, wgt[2] * inv, wgt[3] * inv);
    }
    __syncthreads();

    float acc[4][4];
    #pragma unroll
    for (int j = 0; j < 4; j++)
        #pragma unroll
        for (int e = 0; e < 4; e++) acc[j][e] = 0.f;

    const int a_m0 = t >> 3,         a_k4_0 = t & 7;
    const int a_m1 = (t + 256) >> 3, a_k4_1 = (t + 256) & 7;
    const int b_k0 = t >> 4,         b_n4_0 = t & 15;
    const int b_k1 = (t + 256) >> 4, b_n4_1 = (t + 256) & 15;

    float4 pv[2][4];
    float4 rb0, rb1;
    #pragma unroll
    for (int p = 0; p < 2; p++) {
        int m  = p ? a_m1 : a_m0;
        int d0 = (p ? a_k4_1 : a_k4_0) * 4;
        #pragma unroll
        for (int s = 0; s < 4; s++)
            pv[p][s] = *(const float4*)&g_pav[(((size_t)(s * HEADS + 0)) * N + m0 + m) * DK + d0];
    }
    rb0 = *(const float4*)&W[(size_t)(0 + b_k0) * 256 + n0 + b_n4_0 * 4];
    rb1 = *(const float4*)&W[(size_t)(0 + b_k1) * 256 + n0 + b_n4_1 * 4];

    for (int c = 0; c < 8; c++) {
        const int buf = c & 1;
        {
            #pragma unroll
            for (int p = 0; p < 2; p++) {
                int m  = p ? a_m1 : a_m0;
                int k4 = p ? a_k4_1 : a_k4_0;
                float4 wc = WC[m][c];
                float4 v;
                v.x = wc.x * pv[p][0].x + wc.y * pv[p][1].x + wc.z * pv[p][2].x + wc.w * pv[p][3].x;
                v.y = wc.x * pv[p][0].y + wc.y * pv[p][1].y + wc.z * pv[p][2].y + wc.w * pv[p][3].y;
                v.z = wc.x * pv[p][0].z + wc.y * pv[p][1].z + wc.z * pv[p][2].z + wc.w * pv[p][3].z;
                v.w = wc.x * pv[p][0].w + wc.y * pv[p][1].w + wc.z * pv[p][2].w + wc.w * pv[p][3].w;
                int frag = (m >> 4) * 4 + (k4 >> 1);
                int idx  = (k4 & 1) * 2 + ((m & 15) >> 3);
                uint32_t* dst = (uint32_t*)&AF[buf][frag * 32 + ((m & 7) * 4)];
                dst[0 * 4 + idx] = f2tf(v.x);
                dst[1 * 4 + idx] = f2tf(v.y);
                dst[2 * 4 + idx] = f2tf(v.z);
                dst[3 * 4 + idx] = f2tf(v.w);
            }
            #pragma unroll
            for (int p = 0; p < 2; p++) {
                int k  = p ? b_k1 : b_k0;
                int n4 = p ? b_n4_1 : b_n4_0;
                float4 v = p ? rb1 : rb0;
                int frag = (n4 >> 1) * 4 + (k >> 3);
                int hi   = (k >> 2) & 1;
                uint32_t* dst = (uint32_t*)&BF[buf][frag * 32 + (n4 & 1) * 16 + (k & 3)];
                dst[0 * 8 + hi] = f2tf(v.x);
                dst[1 * 8 + hi] = f2tf(v.y);
                dst[2 * 8 + hi] = f2tf(v.z);
                dst[3 * 8 + hi] = f2tf(v.w);
            }
        }
        __syncthreads();

        if (c < 7) {
            int hh = c + 1;
            #pragma unroll
            for (int p = 0; p < 2; p++) {
                int m  = p ? a_m1 : a_m0;
                int d0 = (p ? a_k4_1 : a_k4_0) * 4;
                #pragma unroll
                for (int s = 0; s < 4; s++)
                    pv[p][s] = *(const float4*)&g_pav[(((size_t)(s * HEADS + hh)) * N + m0 + m) * DK + d0];
            }
            int kt = hh * 32;
            rb0 = *(const float4*)&W[(size_t)(kt + b_k0) * 256 + n0 + b_n4_0 * 4];
            rb1 = *(const float4*)&W[(size_t)(kt + b_k1) * 256 + n0 + b_n4_1 * 4];
        }

        #pragma unroll
        for (int ks = 0; ks < 4; ks++) {
            uint4 a = AF[buf][(mf * 4 + ks) * 32 + lane];
            #pragma unroll
            for (int j = 0; j < 4; j++) {
                uint2 b = BF[buf][((nhalf * 4 + j) * 4 + ks) * 32 + lane];
                mma_tf32(acc[j][0], acc[j][1], acc[j][2], acc[j][3],
                         a.x, a.y, a.z, a.w, b.x, b.y);
            }
        }
    }

    const int row0 = m0 + mf * 16 + g;
    #pragma unroll
    for (int j = 0; j < 4; j++) {
        int col = n0 + nhalf * 32 + j * 8 + 2 * q;
        float2 bz = *(const float2*)&bo[col];
        *(float2*)&out[(size_t)row0 * 256 + col] =
            make_float2(acc[j][0] + bz.x, acc[j][1] + bz.y);
        *(float2*)&out[(size_t)(row0 + 8) * 256 + col] =
            make_float2(acc[j][2] + bz.x, acc[j][3] + bz.y);
    }
}

// -------------------- fp16 flash attention: 2 heads per block --------------
// grid (N/64, HEADS/2, NSPLIT), 256 threads / 8 warps.
// Warps 0-3 -> head 2*by, warps 4-7 -> head 2*by+1; one shared bias tile.
__global__ __launch_bounds__(256) void attn_mma_kernel()
{
    extern __shared__ uint32_t dsm[];
    uint32_t* KBb = dsm;                     // [2 buf][2 head][1024]
    uint32_t* VBb = dsm + 4096;              // [2 buf][2 head][1024]
    __half*   BSb = (__half*)(dsm + 8192);   // [2 buf][64*BSTR]

    const int tid  = threadIdx.x;
    const int lane = tid & 31;
    const int warp = tid >> 5;               // 0..7
    const int whead = warp >> 2;             // 0..1
    const int wq    = warp & 3;              // 0..3
    const int q    = lane & 3;
    const int g    = lane >> 2;
    const int h0 = blockIdx.y * 2;
    const int h  = h0 + whead;
    const int z  = blockIdx.z;
    const int q0 = blockIdx.x * 64;
    const int wr0 = wq * 16;
    const int row = q0 + wr0 + g;

    uint32_t qa[2][4];
    {
        const float* q0p = &g_qh[((size_t)h * N + row) * DK];
        const float* q8p = q0p + 8 * DK;
        #pragma unroll
        for (int ks = 0; ks < 2; ks++) {
            int d = ks * 16 + 2 * q;
            qa[ks][0] = packh2(q0p[d],     q0p[d + 1]);
            qa[ks][1] = packh2(q8p[d],     q8p[d + 1]);
            qa[ks][2] = packh2(q0p[d + 8], q0p[d + 9]);
            qa[ks][3] = packh2(q8p[d + 8], q8p[d + 9]);
        }
    }

    float o[4][4];
    #pragma unroll
    for (int n = 0; n < 4; n++)
        #pragma unroll
        for (int e = 0; e < 4; e++) o[n][e] = 0.f;

    float m0 = -INFINITY, m8 = -INFINITY, l0 = 0.f, l8 = 0.f;

    const int ck0 = (z * KSPAN) / 64;
    const int nch = KSPAN / 64;

    // fill: K/V fragments for BOTH heads + one shared bias tile
    auto fill = [&](int buf, int ck) {
        #pragma unroll
        for (int hd = 0; hd < 2; hd++) {
            const uint4* ks = (const uint4*)&g_kf[(size_t)((h0 + hd) * NCHUNK + ck) * 1024];
            const uint4* vs = (const uint4*)&g_vf[(size_t)((h0 + hd) * NCHUNK + ck) * 1024];
            cp16((uint32_t)__cvta_generic_to_shared(&KBb[(buf * 2 + hd) * 1024 + tid * 4]), ks + tid);
            cp16((uint32_t)__cvta_generic_to_shared(&VBb[(buf * 2 + hd) * 1024 + tid * 4]), vs + tid);
        }
        const __half* bsrc = &g_bias[(size_t)q0 * N + ck * 64];
        __half* bdst = &BSb[buf * 64 * BSTR];
        #pragma unroll
        for (int i = 0; i < 2; i++) {
            int idx = i * 256 + tid;        // 0..511 16B-chunks
            int r = idx >> 3, c8 = idx & 7;
            cp16((uint32_t)__cvta_generic_to_shared(&bdst[r * BSTR + c8 * 8]),
                 &bsrc[(size_t)r * N + c8 * 8]);
        }
    };

    fill(0, ck0);
    asm volatile("cp.async.commit_group;");

    for (int cc = 0; cc < nch; cc++) {
        const int cur = cc & 1;

        if (cc + 1 < nch) {
            fill(1 - cur, ck0 + cc + 1);
            asm volatile("cp.async.commit_group;");
            asm volatile("cp.async.wait_group 1;");
        } else {
            asm volatile("cp.async.wait_group 0;");
        }
        __syncthreads();

        const uint32_t* KBc = &KBb[(cur * 2 + whead) * 1024];
        const uint32_t* VBc = &VBb[(cur * 2 + whead) * 1024];
        const __half*   BSc = &BSb[cur * 64 * BSTR];

        float s[8][4];
        #pragma unroll
        for (int j = 0; j < 8; j++)
            #pragma unroll
            for (int e = 0; e < 4; e++) s[j][e] = 0.f;

        #pragma unroll
        for (int ks = 0; ks < 2; ks++) {
            #pragma unroll
            for (int j = 0; j < 8; j++) {
                uint2 b = *(const uint2*)&KBc[((ks * 8 + j) * 32 + lane) * 2];
                mma_f16(s[j][0], s[j][1], s[j][2], s[j][3],
                        qa[ks][0], qa[ks][1], qa[ks][2], qa[ks][3], b.x, b.y);
            }
        }

        {
            const __half* br0 = &BSc[(wr0 + g) * BSTR];
            const __half* br8 = br0 + 8 * BSTR;
            #pragma unroll
            for (int j = 0; j < 8; j++) {
                float2 b0 = __half22float2(*(const __half2*)&br0[8 * j + 2 * q]);
                float2 b8 = __half22float2(*(const __half2*)&br8[8 * j + 2 * q]);
                s[j][0] += b0.x; s[j][1] += b0.y;
                s[j][2] += b8.x; s[j][3] += b8.y;
            }
        }

        float mx0 = s[0][0], mx8 = s[0][2];
        #pragma unroll
        for (int j = 0; j < 8; j++) {
            mx0 = fmaxf(mx0, fmaxf(s[j][0], s[j][1]));
            mx8 = fmaxf(mx8, fmaxf(s[j][2], s[j][3]));
        }
        mx0 = fmaxf(mx0, __shfl_xor_sync(0xffffffffu, mx0, 1));
        mx0 = fmaxf(mx0, __shfl_xor_sync(0xffffffffu, mx0, 2));
        mx8 = fmaxf(mx8, __shfl_xor_sync(0xffffffffu, mx8, 1));
        mx8 = fmaxf(mx8, __shfl_xor_sync(0xffffffffu, mx8, 2));

        float mn0 = fmaxf(m0, mx0), mn8 = fmaxf(m8, mx8);
        float c0 = __expf(m0 - mn0), c8 = __expf(m8 - mn8);
        m0 = mn0; m8 = mn8;
        l0 *= c0;  l8 *= c8;
        #pragma unroll
        for (int n = 0; n < 4; n++) {
            o[n][0] *= c0; o[n][1] *= c0;
            o[n][2] *= c8; o[n][3] *= c8;
        }

        float p[8][4];
        #pragma unroll
        for (int j = 0; j < 8; j++) {
            p[j][0] = __expf(s[j][0] - m0);
            p[j][1] = __expf(s[j][1] - m0);
            p[j][2] = __expf(s[j][2] - m8);
            p[j][3] = __expf(s[j][3] - m8);
            l0 += p[j][0] + p[j][1];
            l8 += p[j][2] + p[j][3];
        }

        #pragma unroll
        for (int kk = 0; kk < 4; kk++) {
            uint32_t a0 = packh2(p[2 * kk][0],     p[2 * kk][1]);
            uint32_t a1 = packh2(p[2 * kk][2],     p[2 * kk][3]);
            uint32_t a2 = packh2(p[2 * kk + 1][0], p[2 * kk + 1][1]);
            uint32_t a3 = packh2(p[2 * kk + 1][2], p[2 * kk + 1][3]);
            #pragma unroll
            for (int n = 0; n < 4; n++) {
                uint2 b = *(const uint2*)&VBc[((kk * 4 + n) * 32 + lane) * 2];
                mma_f16(o[n][0], o[n][1], o[n][2], o[n][3], a0, a1, a2, a3, b.x, b.y);
            }
        }
        __syncthreads();
    }

    l0 += __shfl_xor_sync(0xffffffffu, l0, 1);
    l0 += __shfl_xor_sync(0xffffffffu, l0, 2);
    l8 += __shfl_xor_sync(0xffffffffu, l8, 1);
    l8 += __shfl_xor_sync(0xffffffffu, l8, 2);

    const int rid = (z * HEADS + h) * N + q0 + wr0 + g;
    if (q == 0) {
        g_pm[rid] = m0;     g_pl[rid] = l0;
        g_pm[rid + 8] = m8; g_pl[rid + 8] = l8;
    }
    float* pav0 = &g_pav[(size_t)rid * DK];
    float* pav8 = &g_pav[(size_t)(rid + 8) * DK];
    #pragma unroll
    for (int n = 0; n < 4; n++) {
        *(float2*)&pav0[8 * n + 2 * q] = make_float2(o[n][0], o[n][1]);
        *(float2*)&pav8[8 * n + 2 * q] = make_float2(o[n][2], o[n][3]);
    }
}

// -------------------- launch ------------------------------------------------
extern "C" void kernel_launch(void* const* d_in, const int* in_sizes, int n_in,
                              void* d_out, int out_size)
{
    const int*   label   = (const int*)  d_in[0];
    const float* dist    = (const float*)d_in[1];
    const float* contact = (const float*)d_in[2];
    const float* q       = (const float*)d_in[3];
    const float* k       = (const float*)d_in[4];
    const float* v       = (const float*)d_in[5];
    const float* Wq = (const float*)d_in[6];  const float* bq = (const float*)d_in[7];
    const float* Wk = (const float*)d_in[8];  const float* bk = (const float*)d_in[9];
    const float* Wv = (const float*)d_in[10]; const float* bv = (const float*)d_in[11];
    const float* Wo = (const float*)d_in[12]; const float* bo = (const float*)d_in[13];
    const float* Wd1 = (const float*)d_in[14]; const float* bd1 = (const float*)d_in[15];
    const float* Wd2 = (const float*)d_in[16]; const float* bd2 = (const float*)d_in[17];
    const float* Wc1 = (const float*)d_in[18]; const float* bc1 = (const float*)d_in[19];
    const float* Wc2 = (const float*)d_in[20]; const float* bc2 = (const float*)d_in[21];
    float* out = (float*)d_out;

    float* p_qh;
    cudaGetSymbolAddress((void**)&p_qh, g_qh);

    bias_kernel<<<(N * N / 4) / 256, 256>>>(label, dist, contact,
                                            Wd1, bd1, Wd2, bd2, Wc1, bc1, Wc2, bc2);

    const float scale = 1.f / sqrtf((float)DK);
    qkv_proj<<<dim3(N / 64, HIDDEN / 64, 3), 256>>>(q, k, v, Wq, Wk, Wv,
                                                    bq, bk, bv, p_qh, scale);

    // smem: K 16KB + V 16KB + bias 2*64*BSTR*2B = 18.4KB  => 51200 B
    const int attn_smem = 8192 * 4 + 2 * 64 * BSTR * 2;
    static int smem_set = 0;
    if (!smem_set) {
        cudaFuncSetAttribute(attn_mma_kernel,
                             cudaFuncAttributeMaxDynamicSharedMemorySize, attn_smem);
        smem_set = 1;
    }
    attn_mma_kernel<<<dim3(N / 64, HEADS / 2, NSPLIT), 256, attn_smem>>>();

    o_proj_fused<<<dim3(N / 64, HIDDEN / 64), 256>>>(Wo, bo, out);
}

// round 12
// speedup vs baseline: 1.1347x; 1.0271x over previous
#include <cuda_runtime.h>
#include <cuda_fp16.h>
#include <math.h>
#include <stdint.h>

#define N 2048
#define HIDDEN 256
#define HEADS 8
#define DK 32
#define NSPLIT 4
#define KSPAN (N / NSPLIT)
#define NCHUNK (N / 64)
#define BSTR 72   // bias smem row stride in halves

// -------------------- scratch (__device__ globals; no allocs allowed) -----
__device__ __half g_bias[N * N];                   // 8 MB fp16 pair bias
__device__ float g_qh[HEADS * N * DK];             // head-major projected q (scaled)
__device__ uint32_t g_kf[HEADS * NCHUNK * 1024];   // fragment-major fp16 K
__device__ uint32_t g_vf[HEADS * NCHUNK * 1024];   // fragment-major fp16 V
// split-K partials
__device__ float g_pm[NSPLIT * HEADS * N];
__device__ float g_pl[NSPLIT * HEADS * N];
__device__ float g_pav[NSPLIT * HEADS * N * DK];

// -------------------- helpers ---------------------------------------------
__device__ __forceinline__ uint32_t f2tf(float f) {
    uint32_t u;
    asm("cvt.rna.tf32.f32 %0, %1;" : "=r"(u) : "f"(f));
    return u;
}

__device__ __forceinline__ uint32_t packh2(float lo, float hi) {
    __half2 h = __floats2half2_rn(lo, hi);
    return *reinterpret_cast<uint32_t*>(&h);
}

__device__ __forceinline__ void mma_tf32(float& d0, float& d1, float& d2, float& d3,
                                         uint32_t a0, uint32_t a1, uint32_t a2, uint32_t a3,
                                         uint32_t b0, uint32_t b1)
{
    asm volatile("mma.sync.aligned.m16n8k8.row.col.f32.tf32.tf32.f32 "
                 "{%0,%1,%2,%3}, {%4,%5,%6,%7}, {%8,%9}, {%0,%1,%2,%3};"
                 : "+f"(d0), "+f"(d1), "+f"(d2), "+f"(d3)
                 : "r"(a0), "r"(a1), "r"(a2), "r"(a3), "r"(b0), "r"(b1));
}

__device__ __forceinline__ void mma_f16(float& d0, float& d1, float& d2, float& d3,
                                        uint32_t a0, uint32_t a1, uint32_t a2, uint32_t a3,
                                        uint32_t b0, uint32_t b1)
{
    asm volatile("mma.sync.aligned.m16n8k16.row.col.f32.f16.f16.f32 "
                 "{%0,%1,%2,%3}, {%4,%5,%6,%7}, {%8,%9}, {%0,%1,%2,%3};"
                 : "+f"(d0), "+f"(d1), "+f"(d2), "+f"(d3)
                 : "r"(a0), "r"(a1), "r"(a2), "r"(a3), "r"(b0), "r"(b1));
}

__device__ __forceinline__ void cp16(uint32_t smem_dst, const void* gsrc) {
    asm volatile("cp.async.cg.shared.global [%0], [%1], 16;"
                 :: "r"(smem_dst), "l"(gsrc));
}

// K fragment word index (fp16x2 packed over d-pairs): B-frag of m16n8k16
__device__ __forceinline__ int kaddr16(int key, int d) {
    return ((d >> 4) * 8 + (key >> 3)) * 64 + ((key & 7) * 4 + ((d & 7) >> 1)) * 2 + ((d >> 3) & 1);
}
// V fragment half index (fp16x2 packed over key-pairs)
__device__ __forceinline__ int vaddr16h(int key, int d) {
    return ((((key >> 4) * 4 + (d >> 3)) * 32 + (d & 7) * 4 + ((key & 7) >> 1)) * 2
            + ((key >> 3) & 1)) * 2 + (key & 1);
}

// -------------------- bias kernel (coef MLP collapse inlined, fp16 out) ----
__global__ void bias_kernel(const int* __restrict__ label,
                            const float* __restrict__ dist,
                            const float* __restrict__ contact,
                            const float* __restrict__ Wd1, const float* __restrict__ bd1,
                            const float* __restrict__ Wd2, const float* __restrict__ bd2,
                            const float* __restrict__ Wc1, const float* __restrict__ bc1,
                            const float* __restrict__ Wc2, const float* __restrict__ bc2)
{
    __shared__ float4 cf;
    if (threadIdx.x == 0) {
        float am = 0.f, al = 0.f, c0 = bd2[0] + bc2[0], cm = 0.f;
        #pragma unroll
        for (int h = 0; h < 16; h++) {
            am += Wd1[h]      * Wd2[h];
            al += Wd1[16 + h] * Wd2[h];
            c0 += bd1[h]      * Wd2[h];
            cm += Wc1[h]      * Wc2[h];
            al += Wc1[16 + h] * Wc2[h];
            c0 += bc1[h]      * Wc2[h];
        }
        cf = make_float4(am, cm, al, c0);
    }
    __syncthreads();
    const float am = cf.x, cm = cf.y, al = cf.z, c0 = cf.w;

    int i = blockIdx.x * blockDim.x + threadIdx.x;
    float4 dm = ((const float4*)dist)[i];
    float4 cv = ((const float4*)contact)[i];
    int4   lb = ((const int4*)label)[i];
    float ox = fmaf(am, dm.x, fmaf(cm, cv.x, fmaf(al, (float)lb.x, c0)));
    float oy = fmaf(am, dm.y, fmaf(cm, cv.y, fmaf(al, (float)lb.y, c0)));
    float oz = fmaf(am, dm.z, fmaf(cm, cv.z, fmaf(al, (float)lb.z, c0)));
    float ow = fmaf(am, dm.w, fmaf(cm, cv.w, fmaf(al, (float)lb.w, c0)));
    uint2 r;
    r.x = packh2(ox, oy);
    r.y = packh2(oz, ow);
    ((uint2*)g_bias)[i] = r;
}

// -------------------- tf32 projection GEMM body (R9: 256thr, 64x64) --------
__device__ __forceinline__ void proj_body(const float* __restrict__ A,
                                          const float* __restrict__ W,
                                          const float* __restrict__ bias,
                                          float* __restrict__ out,
                                          float scale, int mode)
{
    __shared__ uint4 AF[2][16 * 32];
    __shared__ uint2 BF[2][32 * 32];

    const int t    = threadIdx.x;
    const int lane = t & 31;
    const int w    = t >> 5;
    const int q    = lane & 3;
    const int g    = lane >> 2;
    const int m0   = blockIdx.x * 64;
    const int n0   = blockIdx.y * 64;
    const int mf    = w >> 1;
    const int nhalf = w & 1;

    float acc[4][4];
    #pragma unroll
    for (int j = 0; j < 4; j++)
        #pragma unroll
        for (int e = 0; e < 4; e++) acc[j][e] = 0.f;

    const int a_m0 = t >> 3,         a_k4_0 = t & 7;
    const int a_m1 = (t + 256) >> 3, a_k4_1 = (t + 256) & 7;
    const int b_k0 = t >> 4,         b_n4_0 = t & 15;
    const int b_k1 = (t + 256) >> 4, b_n4_1 = (t + 256) & 15;

    float4 ra0, ra1, rb0, rb1;
    ra0 = *(const float4*)&A[(size_t)(m0 + a_m0) * 256 + 0 + a_k4_0 * 4];
    ra1 = *(const float4*)&A[(size_t)(m0 + a_m1) * 256 + 0 + a_k4_1 * 4];
    rb0 = *(const float4*)&W[(size_t)(0 + b_k0) * 256 + n0 + b_n4_0 * 4];
    rb1 = *(const float4*)&W[(size_t)(0 + b_k1) * 256 + n0 + b_n4_1 * 4];

    for (int c = 0; c < 8; c++) {
        const int buf = c & 1;
        {
            #pragma unroll
            for (int p = 0; p < 2; p++) {
                int m  = p ? a_m1 : a_m0;
                int k4 = p ? a_k4_1 : a_k4_0;
                float4 v = p ? ra1 : ra0;
                int frag = (m >> 4) * 4 + (k4 >> 1);
                int idx  = (k4 & 1) * 2 + ((m & 15) >> 3);
                uint32_t* dst = (uint32_t*)&AF[buf][frag * 32 + ((m & 7) * 4)];
                dst[0 * 4 + idx] = f2tf(v.x);
                dst[1 * 4 + idx] = f2tf(v.y);
                dst[2 * 4 + idx] = f2tf(v.z);
                dst[3 * 4 + idx] = f2tf(v.w);
            }
            #pragma unroll
            for (int p = 0; p < 2; p++) {
                int k  = p ? b_k1 : b_k0;
                int n4 = p ? b_n4_1 : b_n4_0;
                float4 v = p ? rb1 : rb0;
                int frag = (n4 >> 1) * 4 + (k >> 3);
                int hi   = (k >> 2) & 1;
                uint32_t* dst = (uint32_t*)&BF[buf][frag * 32 + (n4 & 1) * 16 + (k & 3)];
                dst[0 * 8 + hi] = f2tf(v.x);
                dst[1 * 8 + hi] = f2tf(v.y);
                dst[2 * 8 + hi] = f2tf(v.z);
                dst[3 * 8 + hi] = f2tf(v.w);
            }
        }
        __syncthreads();

        if (c < 7) {
            int kt = (c + 1) * 32;
            ra0 = *(const float4*)&A[(size_t)(m0 + a_m0) * 256 + kt + a_k4_0 * 4];
            ra1 = *(const float4*)&A[(size_t)(m0 + a_m1) * 256 + kt + a_k4_1 * 4];
            rb0 = *(const float4*)&W[(size_t)(kt + b_k0) * 256 + n0 + b_n4_0 * 4];
            rb1 = *(const float4*)&W[(size_t)(kt + b_k1) * 256 + n0 + b_n4_1 * 4];
        }

        #pragma unroll
        for (int ks = 0; ks < 4; ks++) {
            uint4 a = AF[buf][(mf * 4 + ks) * 32 + lane];
            #pragma unroll
            for (int j = 0; j < 4; j++) {
                uint2 b = BF[buf][((nhalf * 4 + j) * 4 + ks) * 32 + lane];
                mma_tf32(acc[j][0], acc[j][1], acc[j][2], acc[j][3],
                         a.x, a.y, a.z, a.w, b.x, b.y);
            }
        }
    }

    const int row0 = m0 + mf * 16 + g;
    const int key0 = mf * 16 + g;
    const int ck   = m0 >> 6;
    #pragma unroll
    for (int j = 0; j < 4; j++) {
        int col = n0 + nhalf * 32 + j * 8 + 2 * q;
        float2 bz = *(const float2*)&bias[col];
        float v00 = acc[j][0] + bz.x, v01 = acc[j][1] + bz.y;
        float v10 = acc[j][2] + bz.x, v11 = acc[j][3] + bz.y;
        if (mode == 0) {
            v00 *= scale; v01 *= scale; v10 *= scale; v11 *= scale;
            size_t base = (size_t)(col >> 5) * ((size_t)N * 32) + (col & 31);
            *(float2*)&out[base + (size_t)row0 * 32]       = make_float2(v00, v01);
            *(float2*)&out[base + (size_t)(row0 + 8) * 32] = make_float2(v10, v11);
        } else {
            int hh = col >> 5, dd = col & 31;
            if (mode == 2) {
                uint32_t* KD = &g_kf[((size_t)hh * NCHUNK + ck) * 1024];
                KD[kaddr16(key0,     dd)] = packh2(v00, v01);
                KD[kaddr16(key0 + 8, dd)] = packh2(v10, v11);
            } else {
                __half* VD = (__half*)&g_vf[((size_t)hh * NCHUNK + ck) * 1024];
                VD[vaddr16h(key0,     dd)]     = __float2half_rn(v00);
                VD[vaddr16h(key0,     dd + 1)] = __float2half_rn(v01);
                VD[vaddr16h(key0 + 8, dd)]     = __float2half_rn(v10);
                VD[vaddr16h(key0 + 8, dd + 1)] = __float2half_rn(v11);
            }
        }
    }
}

__global__ __launch_bounds__(256) void qkv_proj(const float* __restrict__ q,
                                                const float* __restrict__ k,
                                                const float* __restrict__ v,
                                                const float* __restrict__ Wq,
                                                const float* __restrict__ Wk,
                                                const float* __restrict__ Wv,
                                                const float* __restrict__ bq,
                                                const float* __restrict__ bk,
                                                const float* __restrict__ bv,
                                                float* __restrict__ oq,
                                                float scale)
{
    int z = blockIdx.z;
    if (z == 0)      proj_body(q, Wq, bq, oq,      scale, 0);
    else if (z == 1) proj_body(k, Wk, bk, nullptr, 1.f,   2);
    else             proj_body(v, Wv, bv, nullptr, 1.f,   3);
}

// -------------------- O-projection with fused split-K combine (R9) ---------
__global__ __launch_bounds__(256) void o_proj_fused(const float* __restrict__ W,
                                                    const float* __restrict__ bo,
                                                    float* __restrict__ out)
{
    __shared__ uint4 AF[2][16 * 32];
    __shared__ uint2 BF[2][32 * 32];
    __shared__ float4 WC[64][8];

    const int t    = threadIdx.x;
    const int lane = t & 31;
    const int w    = t >> 5;
    const int q    = lane & 3;
    const int g    = lane >> 2;
    const int m0   = blockIdx.x * 64;
    const int n0   = blockIdx.y * 64;
    const int mf    = w >> 1;
    const int nhalf = w & 1;

    #pragma unroll
    for (int p = 0; p < 2; p++) {
        int idx = t + p * 256;
        int r = idx >> 3, hh = idx & 7;
        int row = m0 + r;
        float pm[4], pl[4];
        float M = -INFINITY;
        #pragma unroll
        for (int s = 0; s < 4; s++) {
            pm[s] = g_pm[(s * HEADS + hh) * N + row];
            pl[s] = g_pl[(s * HEADS + hh) * N + row];
            M = fmaxf(M, pm[s]);
        }
        float wgt[4], l = 0.f;
        #pragma unroll
        for (int s = 0; s < 4; s++) { wgt[s] = __expf(pm[s] - M); l += pl[s] * wgt[s]; }
        float inv = 1.f / l;
        WC[r][hh] = make_float4(wgt[0] * inv, wgt[1] * inv, wgt[2] * inv, wgt[3] * inv);
    }
    __syncthreads();

    float acc[4][4];
    #pragma unroll
    for (int j = 0; j < 4; j++)
        #pragma unroll
        for (int e = 0; e < 4; e++) acc[j][e] = 0.f;

    const int a_m0 = t >> 3,         a_k4_0 = t & 7;
    const int a_m1 = (t + 256) >> 3, a_k4_1 = (t + 256) & 7;
    const int b_k0 = t >> 4,         b_n4_0 = t & 15;
    const int b_k1 = (t + 256) >> 4, b_n4_1 = (t + 256) & 15;

    float4 pv[2][4];
    float4 rb0, rb1;
    #pragma unroll
    for (int p = 0; p < 2; p++) {
        int m  = p ? a_m1 : a_m0;
        int d0 = (p ? a_k4_1 : a_k4_0) * 4;
        #pragma unroll
        for (int s = 0; s < 4; s++)
            pv[p][s] = *(const float4*)&g_pav[(((size_t)(s * HEADS + 0)) * N + m0 + m) * DK + d0];
    }
    rb0 = *(const float4*)&W[(size_t)(0 + b_k0) * 256 + n0 + b_n4_0 * 4];
    rb1 = *(const float4*)&W[(size_t)(0 + b_k1) * 256 + n0 + b_n4_1 * 4];

    for (int c = 0; c < 8; c++) {
        const int buf = c & 1;
        {
            #pragma unroll
            for (int p = 0; p < 2; p++) {
                int m  = p ? a_m1 : a_m0;
                int k4 = p ? a_k4_1 : a_k4_0;
                float4 wc = WC[m][c];
                float4 v;
                v.x = wc.x * pv[p][0].x + wc.y * pv[p][1].x + wc.z * pv[p][2].x + wc.w * pv[p][3].x;
                v.y = wc.x * pv[p][0].y + wc.y * pv[p][1].y + wc.z * pv[p][2].y + wc.w * pv[p][3].y;
                v.z = wc.x * pv[p][0].z + wc.y * pv[p][1].z + wc.z * pv[p][2].z + wc.w * pv[p][3].z;
                v.w = wc.x * pv[p][0].w + wc.y * pv[p][1].w + wc.z * pv[p][2].w + wc.w * pv[p][3].w;
                int frag = (m >> 4) * 4 + (k4 >> 1);
                int idx  = (k4 & 1) * 2 + ((m & 15) >> 3);
                uint32_t* dst = (uint32_t*)&AF[buf][frag * 32 + ((m & 7) * 4)];
                dst[0 * 4 + idx] = f2tf(v.x);
                dst[1 * 4 + idx] = f2tf(v.y);
                dst[2 * 4 + idx] = f2tf(v.z);
                dst[3 * 4 + idx] = f2tf(v.w);
            }
            #pragma unroll
            for (int p = 0; p < 2; p++) {
                int k  = p ? b_k1 : b_k0;
                int n4 = p ? b_n4_1 : b_n4_0;
                float4 v = p ? rb1 : rb0;
                int frag = (n4 >> 1) * 4 + (k >> 3);
                int hi   = (k >> 2) & 1;
                uint32_t* dst = (uint32_t*)&BF[buf][frag * 32 + (n4 & 1) * 16 + (k & 3)];
                dst[0 * 8 + hi] = f2tf(v.x);
                dst[1 * 8 + hi] = f2tf(v.y);
                dst[2 * 8 + hi] = f2tf(v.z);
                dst[3 * 8 + hi] = f2tf(v.w);
            }
        }
        __syncthreads();

        if (c < 7) {
            int hh = c + 1;
            #pragma unroll
            for (int p = 0; p < 2; p++) {
                int m  = p ? a_m1 : a_m0;
                int d0 = (p ? a_k4_1 : a_k4_0) * 4;
                #pragma unroll
                for (int s = 0; s < 4; s++)
                    pv[p][s] = *(const float4*)&g_pav[(((size_t)(s * HEADS + hh)) * N + m0 + m) * DK + d0];
            }
            int kt = hh * 32;
            rb0 = *(const float4*)&W[(size_t)(kt + b_k0) * 256 + n0 + b_n4_0 * 4];
            rb1 = *(const float4*)&W[(size_t)(kt + b_k1) * 256 + n0 + b_n4_1 * 4];
        }

        #pragma unroll
        for (int ks = 0; ks < 4; ks++) {
            uint4 a = AF[buf][(mf * 4 + ks) * 32 + lane];
            #pragma unroll
            for (int j = 0; j < 4; j++) {
                uint2 b = BF[buf][((nhalf * 4 + j) * 4 + ks) * 32 + lane];
                mma_tf32(acc[j][0], acc[j][1], acc[j][2], acc[j][3],
                         a.x, a.y, a.z, a.w, b.x, b.y);
            }
        }
    }

    const int row0 = m0 + mf * 16 + g;
    #pragma unroll
    for (int j = 0; j < 4; j++) {
        int col = n0 + nhalf * 32 + j * 8 + 2 * q;
        float2 bz = *(const float2*)&bo[col];
        *(float2*)&out[(size_t)row0 * 256 + col] =
            make_float2(acc[j][0] + bz.x, acc[j][1] + bz.y);
        *(float2*)&out[(size_t)(row0 + 8) * 256 + col] =
            make_float2(acc[j][2] + bz.x, acc[j][3] + bz.y);
    }
}

// -------------------- fp16 flash attention: 32 q-rows per warp -------------
// grid (N/128, HEADS, NSPLIT), 128 threads / 4 warps.
// Each warp owns 2 m16 fragments (rows wr0..wr0+31); every K/V B-fragment
// LDS feeds two mma. Single head per block (R9 topology preserved).
__global__ __launch_bounds__(128) void attn_mma_kernel()
{
    extern __shared__ uint32_t dsm[];
    uint32_t* KBb = dsm;                     // [2][1024]
    uint32_t* VBb = dsm + 2048;              // [2][1024]
    __half*   BSb = (__half*)(dsm + 4096);   // [2][128*BSTR]

    const int tid  = threadIdx.x;
    const int lane = tid & 31;
    const int warp = tid >> 5;
    const int q    = lane & 3;
    const int g    = lane >> 2;
    const int h  = blockIdx.y;
    const int z  = blockIdx.z;
    const int q0 = blockIdx.x * 128;
    const int wr0 = warp * 32;

    // Q A-fragments for both 16-row tiles
    uint32_t qa[2][2][4];
    #pragma unroll
    for (int qi = 0; qi < 2; qi++) {
        const float* q0p = &g_qh[((size_t)h * N + q0 + wr0 + qi * 16 + g) * DK];
        const float* q8p = q0p + 8 * DK;
        #pragma unroll
        for (int ks = 0; ks < 2; ks++) {
            int d = ks * 16 + 2 * q;
            qa[qi][ks][0] = packh2(q0p[d],     q0p[d + 1]);
            qa[qi][ks][1] = packh2(q8p[d],     q8p[d + 1]);
            qa[qi][ks][2] = packh2(q0p[d + 8], q0p[d + 9]);
            qa[qi][ks][3] = packh2(q8p[d + 8], q8p[d + 9]);
        }
    }

    float o[2][4][4];
    #pragma unroll
    for (int qi = 0; qi < 2; qi++)
        #pragma unroll
        for (int n = 0; n < 4; n++)
            #pragma unroll
            for (int e = 0; e < 4; e++) o[qi][n][e] = 0.f;

    float mM[2][2] = {{-INFINITY, -INFINITY}, {-INFINITY, -INFINITY}};
    float lL[2][2] = {{0.f, 0.f}, {0.f, 0.f}};

    const int ck0 = (z * KSPAN) / 64;
    const int nch = KSPAN / 64;

    auto fill = [&](int buf, int ck) {
        const uint4* ks = (const uint4*)&g_kf[(size_t)(h * NCHUNK + ck) * 1024];
        const uint4* vs = (const uint4*)&g_vf[(size_t)(h * NCHUNK + ck) * 1024];
        #pragma unroll
        for (int i = 0; i < 2; i++) {
            int idx = i * 128 + tid;
            cp16((uint32_t)__cvta_generic_to_shared(&KBb[buf * 1024 + idx * 4]), ks + idx);
            cp16((uint32_t)__cvta_generic_to_shared(&VBb[buf * 1024 + idx * 4]), vs + idx);
        }
        const __half* bsrc = &g_bias[(size_t)q0 * N + ck * 64];
        __half* bdst = &BSb[buf * 128 * BSTR];
        #pragma unroll
        for (int i = 0; i < 8; i++) {
            int idx = i * 128 + tid;        // 0..1023 16B-chunks (128 rows x 8)
            int r = idx >> 3, c8 = idx & 7;
            cp16((uint32_t)__cvta_generic_to_shared(&bdst[r * BSTR + c8 * 8]),
                 &bsrc[(size_t)r * N + c8 * 8]);
        }
    };

    fill(0, ck0);
    asm volatile("cp.async.commit_group;");

    for (int cc = 0; cc < nch; cc++) {
        const int cur = cc & 1;

        if (cc + 1 < nch) {
            fill(1 - cur, ck0 + cc + 1);
            asm volatile("cp.async.commit_group;");
            asm volatile("cp.async.wait_group 1;");
        } else {
            asm volatile("cp.async.wait_group 0;");
        }
        __syncthreads();

        const uint32_t* KBc = &KBb[cur * 1024];
        const uint32_t* VBc = &VBb[cur * 1024];
        const __half*   BSc = &BSb[cur * 128 * BSTR];

        // ---- S = Q @ K^T for both q-tiles (each B-frag LDS feeds 2 mma) ----
        float s[2][8][4];
        #pragma unroll
        for (int qi = 0; qi < 2; qi++)
            #pragma unroll
            for (int j = 0; j < 8; j++)
                #pragma unroll
                for (int e = 0; e < 4; e++) s[qi][j][e] = 0.f;

        #pragma unroll
        for (int ks = 0; ks < 2; ks++) {
            #pragma unroll
            for (int j = 0; j < 8; j++) {
                uint2 b = *(const uint2*)&KBc[((ks * 8 + j) * 32 + lane) * 2];
                mma_f16(s[0][j][0], s[0][j][1], s[0][j][2], s[0][j][3],
                        qa[0][ks][0], qa[0][ks][1], qa[0][ks][2], qa[0][ks][3], b.x, b.y);
                mma_f16(s[1][j][0], s[1][j][1], s[1][j][2], s[1][j][3],
                        qa[1][ks][0], qa[1][ks][1], qa[1][ks][2], qa[1][ks][3], b.x, b.y);
            }
        }

        // ---- + bias, softmax per q-tile ----
        #pragma unroll
        for (int qi = 0; qi < 2; qi++) {
            const __half* br0 = &BSc[(wr0 + qi * 16 + g) * BSTR];
            const __half* br8 = br0 + 8 * BSTR;
            #pragma unroll
            for (int j = 0; j < 8; j++) {
                float2 b0 = __half22float2(*(const __half2*)&br0[8 * j + 2 * q]);
                float2 b8 = __half22float2(*(const __half2*)&br8[8 * j + 2 * q]);
                s[qi][j][0] += b0.x; s[qi][j][1] += b0.y;
                s[qi][j][2] += b8.x; s[qi][j][3] += b8.y;
            }

            float mx0 = s[qi][0][0], mx8 = s[qi][0][2];
            #pragma unroll
            for (int j = 0; j < 8; j++) {
                mx0 = fmaxf(mx0, fmaxf(s[qi][j][0], s[qi][j][1]));
                mx8 = fmaxf(mx8, fmaxf(s[qi][j][2], s[qi][j][3]));
            }
            mx0 = fmaxf(mx0, __shfl_xor_sync(0xffffffffu, mx0, 1));
            mx0 = fmaxf(mx0, __shfl_xor_sync(0xffffffffu, mx0, 2));
            mx8 = fmaxf(mx8, __shfl_xor_sync(0xffffffffu, mx8, 1));
            mx8 = fmaxf(mx8, __shfl_xor_sync(0xffffffffu, mx8, 2));

            float mn0 = fmaxf(mM[qi][0], mx0), mn8 = fmaxf(mM[qi][1], mx8);
            float c0 = __expf(mM[qi][0] - mn0), c8 = __expf(mM[qi][1] - mn8);
            mM[qi][0] = mn0; mM[qi][1] = mn8;
            lL[qi][0] *= c0; lL[qi][1] *= c8;
            #pragma unroll
            for (int n = 0; n < 4; n++) {
                o[qi][n][0] *= c0; o[qi][n][1] *= c0;
                o[qi][n][2] *= c8; o[qi][n][3] *= c8;
            }

            // overwrite s with p = exp(s - m)
            #pragma unroll
            for (int j = 0; j < 8; j++) {
                s[qi][j][0] = __expf(s[qi][j][0] - mn0);
                s[qi][j][1] = __expf(s[qi][j][1] - mn0);
                s[qi][j][2] = __expf(s[qi][j][2] - mn8);
                s[qi][j][3] = __expf(s[qi][j][3] - mn8);
                lL[qi][0] += s[qi][j][0] + s[qi][j][1];
                lL[qi][1] += s[qi][j][2] + s[qi][j][3];
            }
        }

        // ---- O += P @ V (each V B-frag LDS feeds 2 mma) ----
        #pragma unroll
        for (int kk = 0; kk < 4; kk++) {
            uint32_t a[2][4];
            #pragma unroll
            for (int qi = 0; qi < 2; qi++) {
                a[qi][0] = packh2(s[qi][2 * kk][0],     s[qi][2 * kk][1]);
                a[qi][1] = packh2(s[qi][2 * kk][2],     s[qi][2 * kk][3]);
                a[qi][2] = packh2(s[qi][2 * kk + 1][0], s[qi][2 * kk + 1][1]);
                a[qi][3] = packh2(s[qi][2 * kk + 1][2], s[qi][2 * kk + 1][3]);
            }
            #pragma unroll
            for (int n = 0; n < 4; n++) {
                uint2 b = *(const uint2*)&VBc[((kk * 4 + n) * 32 + lane) * 2];
                mma_f16(o[0][n][0], o[0][n][1], o[0][n][2], o[0][n][3],
                        a[0][0], a[0][1], a[0][2], a[0][3], b.x, b.y);
                mma_f16(o[1][n][0], o[1][n][1], o[1][n][2], o[1][n][3],
                        a[1][0], a[1][1], a[1][2], a[1][3], b.x, b.y);
            }
        }
        __syncthreads();
    }

    #pragma unroll
    for (int qi = 0; qi < 2; qi++) {
        float l0 = lL[qi][0], l8 = lL[qi][1];
        l0 += __shfl_xor_sync(0xffffffffu, l0, 1);
        l0 += __shfl_xor_sync(0xffffffffu, l0, 2);
        l8 += __shfl_xor_sync(0xffffffffu, l8, 1);
        l8 += __shfl_xor_sync(0xffffffffu, l8, 2);

        const int rid = (z * HEADS + h) * N + q0 + wr0 + qi * 16 + g;
        if (q == 0) {
            g_pm[rid] = mM[qi][0];     g_pl[rid] = l0;
            g_pm[rid + 8] = mM[qi][1]; g_pl[rid + 8] = l8;
        }
        float* pav0 = &g_pav[(size_t)rid * DK];
        float* pav8 = &g_pav[(size_t)(rid + 8) * DK];
        #pragma unroll
        for (int n = 0; n < 4; n++) {
            *(float2*)&pav0[8 * n + 2 * q] = make_float2(o[qi][n][0], o[qi][n][1]);
            *(float2*)&pav8[8 * n + 2 * q] = make_float2(o[qi][n][2], o[qi][n][3]);
        }
    }
}

// -------------------- launch ------------------------------------------------
extern "C" void kernel_launch(void* const* d_in, const int* in_sizes, int n_in,
                              void* d_out, int out_size)
{
    const int*   label   = (const int*)  d_in[0];
    const float* dist    = (const float*)d_in[1];
    const float* contact = (const float*)d_in[2];
    const float* q       = (const float*)d_in[3];
    const float* k       = (const float*)d_in[4];
    const float* v       = (const float*)d_in[5];
    const float* Wq = (const float*)d_in[6];  const float* bq = (const float*)d_in[7];
    const float* Wk = (const float*)d_in[8];  const float* bk = (const float*)d_in[9];
    const float* Wv = (const float*)d_in[10]; const float* bv = (const float*)d_in[11];
    const float* Wo = (const float*)d_in[12]; const float* bo = (const float*)d_in[13];
    const float* Wd1 = (const float*)d_in[14]; const float* bd1 = (const float*)d_in[15];
    const float* Wd2 = (const float*)d_in[16]; const float* bd2 = (const float*)d_in[17];
    const float* Wc1 = (const float*)d_in[18]; const float* bc1 = (const float*)d_in[19];
    const float* Wc2 = (const float*)d_in[20]; const float* bc2 = (const float*)d_in[21];
    float* out = (float*)d_out;

    float* p_qh;
    cudaGetSymbolAddress((void**)&p_qh, g_qh);

    bias_kernel<<<(N * N / 4) / 256, 256>>>(label, dist, contact,
                                            Wd1, bd1, Wd2, bd2, Wc1, bc1, Wc2, bc2);

    const float scale = 1.f / sqrtf((float)DK);
    qkv_proj<<<dim3(N / 64, HIDDEN / 64, 3), 256>>>(q, k, v, Wq, Wk, Wv,
                                                    bq, bk, bv, p_qh, scale);

    // smem: K/V 16KB + bias 2*128*BSTR*2B = 36.9KB => 53248 B
    const int attn_smem = 4096 * 4 + 2 * 128 * BSTR * 2;
    static int smem_set = 0;
    if (!smem_set) {
        cudaFuncSetAttribute(attn_mma_kernel,
                             cudaFuncAttributeMaxDynamicSharedMemorySize, attn_smem);
        smem_set = 1;
    }
    attn_mma_kernel<<<dim3(N / 128, HEADS, NSPLIT), 128, attn_smem>>>();

    o_proj_fused<<<dim3(N / 64, HIDDEN / 64), 256>>>(Wo, bo, out);
}

// round 13
// speedup vs baseline: 1.1871x; 1.0462x over previous
#include <cuda_runtime.h>
#include <cuda_fp16.h>
#include <math.h>
#include <stdint.h>

#define N 2048
#define HIDDEN 256
#define HEADS 8
#define DK 32
#define NSPLIT 2
#define KSPAN (N / NSPLIT)
#define NCHUNK (N / 64)
#define BSTR 72   // bias smem row stride in halves

// -------------------- scratch (__device__ globals; no allocs allowed) -----
__device__ __half g_bias[N * N];                   // 8 MB fp16 pair bias
__device__ float g_qh[HEADS * N * DK];             // head-major projected q (scaled)
__device__ uint32_t g_kf[HEADS * NCHUNK * 1024];   // fragment-major fp16 K
__device__ uint32_t g_vf[HEADS * NCHUNK * 1024];   // fragment-major fp16 V
// split-K partials (NSPLIT=2 -> 4 MB)
__device__ float g_pm[NSPLIT * HEADS * N];
__device__ float g_pl[NSPLIT * HEADS * N];
__device__ float g_pav[NSPLIT * HEADS * N * DK];

// -------------------- helpers ---------------------------------------------
__device__ __forceinline__ uint32_t f2tf(float f) {
    uint32_t u;
    asm("cvt.rna.tf32.f32 %0, %1;" : "=r"(u) : "f"(f));
    return u;
}

__device__ __forceinline__ uint32_t packh2(float lo, float hi) {
    __half2 h = __floats2half2_rn(lo, hi);
    return *reinterpret_cast<uint32_t*>(&h);
}

__device__ __forceinline__ void mma_tf32(float& d0, float& d1, float& d2, float& d3,
                                         uint32_t a0, uint32_t a1, uint32_t a2, uint32_t a3,
                                         uint32_t b0, uint32_t b1)
{
    asm volatile("mma.sync.aligned.m16n8k8.row.col.f32.tf32.tf32.f32 "
                 "{%0,%1,%2,%3}, {%4,%5,%6,%7}, {%8,%9}, {%0,%1,%2,%3};"
                 : "+f"(d0), "+f"(d1), "+f"(d2), "+f"(d3)
                 : "r"(a0), "r"(a1), "r"(a2), "r"(a3), "r"(b0), "r"(b1));
}

__device__ __forceinline__ void mma_f16(float& d0, float& d1, float& d2, float& d3,
                                        uint32_t a0, uint32_t a1, uint32_t a2, uint32_t a3,
                                        uint32_t b0, uint32_t b1)
{
    asm volatile("mma.sync.aligned.m16n8k16.row.col.f32.f16.f16.f32 "
                 "{%0,%1,%2,%3}, {%4,%5,%6,%7}, {%8,%9}, {%0,%1,%2,%3};"
                 : "+f"(d0), "+f"(d1), "+f"(d2), "+f"(d3)
                 : "r"(a0), "r"(a1), "r"(a2), "r"(a3), "r"(b0), "r"(b1));
}

__device__ __forceinline__ void cp16(uint32_t smem_dst, const void* gsrc) {
    asm volatile("cp.async.cg.shared.global [%0], [%1], 16;"
                 :: "r"(smem_dst), "l"(gsrc));
}

// K fragment word index (fp16x2 packed over d-pairs): B-frag of m16n8k16
__device__ __forceinline__ int kaddr16(int key, int d) {
    return ((d >> 4) * 8 + (key >> 3)) * 64 + ((key & 7) * 4 + ((d & 7) >> 1)) * 2 + ((d >> 3) & 1);
}
// V fragment half index (fp16x2 packed over key-pairs)
__device__ __forceinline__ int vaddr16h(int key, int d) {
    return ((((key >> 4) * 4 + (d >> 3)) * 32 + (d & 7) * 4 + ((key & 7) >> 1)) * 2
            + ((key >> 3) & 1)) * 2 + (key & 1);
}

// -------------------- bias kernel (coef MLP collapse inlined, fp16 out) ----
__global__ void bias_kernel(const int* __restrict__ label,
                            const float* __restrict__ dist,
                            const float* __restrict__ contact,
                            const float* __restrict__ Wd1, const float* __restrict__ bd1,
                            const float* __restrict__ Wd2, const float* __restrict__ bd2,
                            const float* __restrict__ Wc1, const float* __restrict__ bc1,
                            const float* __restrict__ Wc2, const float* __restrict__ bc2)
{
    __shared__ float4 cf;
    if (threadIdx.x == 0) {
        float am = 0.f, al = 0.f, c0 = bd2[0] + bc2[0], cm = 0.f;
        #pragma unroll
        for (int h = 0; h < 16; h++) {
            am += Wd1[h]      * Wd2[h];
            al += Wd1[16 + h] * Wd2[h];
            c0 += bd1[h]      * Wd2[h];
            cm += Wc1[h]      * Wc2[h];
            al += Wc1[16 + h] * Wc2[h];
            c0 += bc1[h]      * Wc2[h];
        }
        cf = make_float4(am, cm, al, c0);
    }
    __syncthreads();
    const float am = cf.x, cm = cf.y, al = cf.z, c0 = cf.w;

    int i = blockIdx.x * blockDim.x + threadIdx.x;
    float4 dm = ((const float4*)dist)[i];
    float4 cv = ((const float4*)contact)[i];
    int4   lb = ((const int4*)label)[i];
    float ox = fmaf(am, dm.x, fmaf(cm, cv.x, fmaf(al, (float)lb.x, c0)));
    float oy = fmaf(am, dm.y, fmaf(cm, cv.y, fmaf(al, (float)lb.y, c0)));
    float oz = fmaf(am, dm.z, fmaf(cm, cv.z, fmaf(al, (float)lb.z, c0)));
    float ow = fmaf(am, dm.w, fmaf(cm, cv.w, fmaf(al, (float)lb.w, c0)));
    uint2 r;
    r.x = packh2(ox, oy);
    r.y = packh2(oz, ow);
    ((uint2*)g_bias)[i] = r;
}

// -------------------- tf32 projection GEMM body (R9: 256thr, 64x64) --------
__device__ __forceinline__ void proj_body(const float* __restrict__ A,
                                          const float* __restrict__ W,
                                          const float* __restrict__ bias,
                                          float* __restrict__ out,
                                          float scale, int mode)
{
    __shared__ uint4 AF[2][16 * 32];
    __shared__ uint2 BF[2][32 * 32];

    const int t    = threadIdx.x;
    const int lane = t & 31;
    const int w    = t >> 5;
    const int q    = lane & 3;
    const int g    = lane >> 2;
    const int m0   = blockIdx.x * 64;
    const int n0   = blockIdx.y * 64;
    const int mf    = w >> 1;
    const int nhalf = w & 1;

    float acc[4][4];
    #pragma unroll
    for (int j = 0; j < 4; j++)
        #pragma unroll
        for (int e = 0; e < 4; e++) acc[j][e] = 0.f;

    const int a_m0 = t >> 3,         a_k4_0 = t & 7;
    const int a_m1 = (t + 256) >> 3, a_k4_1 = (t + 256) & 7;
    const int b_k0 = t >> 4,         b_n4_0 = t & 15;
    const int b_k1 = (t + 256) >> 4, b_n4_1 = (t + 256) & 15;

    float4 ra0, ra1, rb0, rb1;
    ra0 = *(const float4*)&A[(size_t)(m0 + a_m0) * 256 + 0 + a_k4_0 * 4];
    ra1 = *(const float4*)&A[(size_t)(m0 + a_m1) * 256 + 0 + a_k4_1 * 4];
    rb0 = *(const float4*)&W[(size_t)(0 + b_k0) * 256 + n0 + b_n4_0 * 4];
    rb1 = *(const float4*)&W[(size_t)(0 + b_k1) * 256 + n0 + b_n4_1 * 4];

    for (int c = 0; c < 8; c++) {
        const int buf = c & 1;
        {
            #pragma unroll
            for (int p = 0; p < 2; p++) {
                int m  = p ? a_m1 : a_m0;
                int k4 = p ? a_k4_1 : a_k4_0;
                float4 v = p ? ra1 : ra0;
                int frag = (m >> 4) * 4 + (k4 >> 1);
                int idx  = (k4 & 1) * 2 + ((m & 15) >> 3);
                uint32_t* dst = (uint32_t*)&AF[buf][frag * 32 + ((m & 7) * 4)];
                dst[0 * 4 + idx] = f2tf(v.x);
                dst[1 * 4 + idx] = f2tf(v.y);
                dst[2 * 4 + idx] = f2tf(v.z);
                dst[3 * 4 + idx] = f2tf(v.w);
            }
            #pragma unroll
            for (int p = 0; p < 2; p++) {
                int k  = p ? b_k1 : b_k0;
                int n4 = p ? b_n4_1 : b_n4_0;
                float4 v = p ? rb1 : rb0;
                int frag = (n4 >> 1) * 4 + (k >> 3);
                int hi   = (k >> 2) & 1;
                uint32_t* dst = (uint32_t*)&BF[buf][frag * 32 + (n4 & 1) * 16 + (k & 3)];
                dst[0 * 8 + hi] = f2tf(v.x);
                dst[1 * 8 + hi] = f2tf(v.y);
                dst[2 * 8 + hi] = f2tf(v.z);
                dst[3 * 8 + hi] = f2tf(v.w);
            }
        }
        __syncthreads();

        if (c < 7) {
            int kt = (c + 1) * 32;
            ra0 = *(const float4*)&A[(size_t)(m0 + a_m0) * 256 + kt + a_k4_0 * 4];
            ra1 = *(const float4*)&A[(size_t)(m0 + a_m1) * 256 + kt + a_k4_1 * 4];
            rb0 = *(const float4*)&W[(size_t)(kt + b_k0) * 256 + n0 + b_n4_0 * 4];
            rb1 = *(const float4*)&W[(size_t)(kt + b_k1) * 256 + n0 + b_n4_1 * 4];
        }

        #pragma unroll
        for (int ks = 0; ks < 4; ks++) {
            uint4 a = AF[buf][(mf * 4 + ks) * 32 + lane];
            #pragma unroll
            for (int j = 0; j < 4; j++) {
                uint2 b = BF[buf][((nhalf * 4 + j) * 4 + ks) * 32 + lane];
                mma_tf32(acc[j][0], acc[j][1], acc[j][2], acc[j][3],
                         a.x, a.y, a.z, a.w, b.x, b.y);
            }
        }
    }

    const int row0 = m0 + mf * 16 + g;
    const int key0 = mf * 16 + g;
    const int ck   = m0 >> 6;
    #pragma unroll
    for (int j = 0; j < 4; j++) {
        int col = n0 + nhalf * 32 + j * 8 + 2 * q;
        float2 bz = *(const float2*)&bias[col];
        float v00 = acc[j][0] + bz.x, v01 = acc[j][1] + bz.y;
        float v10 = acc[j][2] + bz.x, v11 = acc[j][3] + bz.y;
        if (mode == 0) {
            v00 *= scale; v01 *= scale; v10 *= scale; v11 *= scale;
            size_t base = (size_t)(col >> 5) * ((size_t)N * 32) + (col & 31);
            *(float2*)&out[base + (size_t)row0 * 32]       = make_float2(v00, v01);
            *(float2*)&out[base + (size_t)(row0 + 8) * 32] = make_float2(v10, v11);
        } else {
            int hh = col >> 5, dd = col & 31;
            if (mode == 2) {
                uint32_t* KD = &g_kf[((size_t)hh * NCHUNK + ck) * 1024];
                KD[kaddr16(key0,     dd)] = packh2(v00, v01);
                KD[kaddr16(key0 + 8, dd)] = packh2(v10, v11);
            } else {
                __half* VD = (__half*)&g_vf[((size_t)hh * NCHUNK + ck) * 1024];
                VD[vaddr16h(key0,     dd)]     = __float2half_rn(v00);
                VD[vaddr16h(key0,     dd + 1)] = __float2half_rn(v01);
                VD[vaddr16h(key0 + 8, dd)]     = __float2half_rn(v10);
                VD[vaddr16h(key0 + 8, dd + 1)] = __float2half_rn(v11);
            }
        }
    }
}

__global__ __launch_bounds__(256) void qkv_proj(const float* __restrict__ q,
                                                const float* __restrict__ k,
                                                const float* __restrict__ v,
                                                const float* __restrict__ Wq,
                                                const float* __restrict__ Wk,
                                                const float* __restrict__ Wv,
                                                const float* __restrict__ bq,
                                                const float* __restrict__ bk,
                                                const float* __restrict__ bv,
                                                float* __restrict__ oq,
                                                float scale)
{
    int z = blockIdx.z;
    if (z == 0)      proj_body(q, Wq, bq, oq,      scale, 0);
    else if (z == 1) proj_body(k, Wk, bk, nullptr, 1.f,   2);
    else             proj_body(v, Wv, bv, nullptr, 1.f,   3);
}

// -------------------- O-projection with fused 2-way split-K combine --------
__global__ __launch_bounds__(256) void o_proj_fused(const float* __restrict__ W,
                                                    const float* __restrict__ bo,
                                                    float* __restrict__ out)
{
    __shared__ uint4 AF[2][16 * 32];
    __shared__ uint2 BF[2][32 * 32];
    __shared__ float2 WC[64][8];       // [row_local][head] = (w0/l, w1/l)

    const int t    = threadIdx.x;
    const int lane = t & 31;
    const int w    = t >> 5;
    const int q    = lane & 3;
    const int g    = lane >> 2;
    const int m0   = blockIdx.x * 64;
    const int n0   = blockIdx.y * 64;
    const int mf    = w >> 1;
    const int nhalf = w & 1;

    #pragma unroll
    for (int p = 0; p < 2; p++) {
        int idx = t + p * 256;
        int r = idx >> 3, hh = idx & 7;
        int row = m0 + r;
        float pm0 = g_pm[(0 * HEADS + hh) * N + row];
        float pm1 = g_pm[(1 * HEADS + hh) * N + row];
        float pl0 = g_pl[(0 * HEADS + hh) * N + row];
        float pl1 = g_pl[(1 * HEADS + hh) * N + row];
        float M = fmaxf(pm0, pm1);
        float w0 = __expf(pm0 - M), w1 = __expf(pm1 - M);
        float inv = 1.f / (pl0 * w0 + pl1 * w1);
        WC[r][hh] = make_float2(w0 * inv, w1 * inv);
    }
    __syncthreads();

    float acc[4][4];
    #pragma unroll
    for (int j = 0; j < 4; j++)
        #pragma unroll
        for (int e = 0; e < 4; e++) acc[j][e] = 0.f;

    const int a_m0 = t >> 3,         a_k4_0 = t & 7;
    const int a_m1 = (t + 256) >> 3, a_k4_1 = (t + 256) & 7;
    const int b_k0 = t >> 4,         b_n4_0 = t & 15;
    const int b_k1 = (t + 256) >> 4, b_n4_1 = (t + 256) & 15;

    float4 pv[2][2];
    float4 rb0, rb1;
    #pragma unroll
    for (int p = 0; p < 2; p++) {
        int m  = p ? a_m1 : a_m0;
        int d0 = (p ? a_k4_1 : a_k4_0) * 4;
        #pragma unroll
        for (int s = 0; s < NSPLIT; s++)
            pv[p][s] = *(const float4*)&g_pav[(((size_t)(s * HEADS + 0)) * N + m0 + m) * DK + d0];
    }
    rb0 = *(const float4*)&W[(size_t)(0 + b_k0) * 256 + n0 + b_n4_0 * 4];
    rb1 = *(const float4*)&W[(size_t)(0 + b_k1) * 256 + n0 + b_n4_1 * 4];

    for (int c = 0; c < 8; c++) {
        const int buf = c & 1;
        {
            #pragma unroll
            for (int p = 0; p < 2; p++) {
                int m  = p ? a_m1 : a_m0;
                int k4 = p ? a_k4_1 : a_k4_0;
                float2 wc = WC[m][c];
                float4 v;
                v.x = wc.x * pv[p][0].x + wc.y * pv[p][1].x;
                v.y = wc.x * pv[p][0].y + wc.y * pv[p][1].y;
                v.z = wc.x * pv[p][0].z + wc.y * pv[p][1].z;
                v.w = wc.x * pv[p][0].w + wc.y * pv[p][1].w;
                int frag = (m >> 4) * 4 + (k4 >> 1);
                int idx  = (k4 & 1) * 2 + ((m & 15) >> 3);
                uint32_t* dst = (uint32_t*)&AF[buf][frag * 32 + ((m & 7) * 4)];
                dst[0 * 4 + idx] = f2tf(v.x);
                dst[1 * 4 + idx] = f2tf(v.y);
                dst[2 * 4 + idx] = f2tf(v.z);
                dst[3 * 4 + idx] = f2tf(v.w);
            }
            #pragma unroll
            for (int p = 0; p < 2; p++) {
                int k  = p ? b_k1 : b_k0;
                int n4 = p ? b_n4_1 : b_n4_0;
                float4 v = p ? rb1 : rb0;
                int frag = (n4 >> 1) * 4 + (k >> 3);
                int hi   = (k >> 2) & 1;
                uint32_t* dst = (uint32_t*)&BF[buf][frag * 32 + (n4 & 1) * 16 + (k & 3)];
                dst[0 * 8 + hi] = f2tf(v.x);
                dst[1 * 8 + hi] = f2tf(v.y);
                dst[2 * 8 + hi] = f2tf(v.z);
                dst[3 * 8 + hi] = f2tf(v.w);
            }
        }
        __syncthreads();

        if (c < 7) {
            int hh = c + 1;
            #pragma unroll
            for (int p = 0; p < 2; p++) {
                int m  = p ? a_m1 : a_m0;
                int d0 = (p ? a_k4_1 : a_k4_0) * 4;
                #pragma unroll
                for (int s = 0; s < NSPLIT; s++)
                    pv[p][s] = *(const float4*)&g_pav[(((size_t)(s * HEADS + hh)) * N + m0 + m) * DK + d0];
            }
            int kt = hh * 32;
            rb0 = *(const float4*)&W[(size_t)(kt + b_k0) * 256 + n0 + b_n4_0 * 4];
            rb1 = *(const float4*)&W[(size_t)(kt + b_k1) * 256 + n0 + b_n4_1 * 4];
        }

        #pragma unroll
        for (int ks = 0; ks < 4; ks++) {
            uint4 a = AF[buf][(mf * 4 + ks) * 32 + lane];
            #pragma unroll
            for (int j = 0; j < 4; j++) {
                uint2 b = BF[buf][((nhalf * 4 + j) * 4 + ks) * 32 + lane];
                mma_tf32(acc[j][0], acc[j][1], acc[j][2], acc[j][3],
                         a.x, a.y, a.z, a.w, b.x, b.y);
            }
        }
    }

    const int row0 = m0 + mf * 16 + g;
    #pragma unroll
    for (int j = 0; j < 4; j++) {
        int col = n0 + nhalf * 32 + j * 8 + 2 * q;
        float2 bz = *(const float2*)&bo[col];
        *(float2*)&out[(size_t)row0 * 256 + col] =
            make_float2(acc[j][0] + bz.x, acc[j][1] + bz.y);
        *(float2*)&out[(size_t)(row0 + 8) * 256 + col] =
            make_float2(acc[j][2] + bz.x, acc[j][3] + bz.y);
    }
}

// -------------------- fp16 flash attention (R9 shape, NSPLIT=2) ------------
// grid (N/64, HEADS, NSPLIT), 128 threads / 4 warps, 16 q-rows per warp.
__global__ __launch_bounds__(128) void attn_mma_kernel()
{
    extern __shared__ uint32_t dsm[];
    uint32_t* KBb = dsm;                     // [2][1024]
    uint32_t* VBb = dsm + 2048;              // [2][1024]
    __half*   BSb = (__half*)(dsm + 4096);   // [2][64*BSTR]

    const int tid  = threadIdx.x;
    const int lane = tid & 31;
    const int warp = tid >> 5;
    const int q    = lane & 3;
    const int g    = lane >> 2;
    const int h  = blockIdx.y;
    const int z  = blockIdx.z;
    const int q0 = blockIdx.x * 64;
    const int wr0 = warp * 16;
    const int row = q0 + wr0 + g;

    uint32_t qa[2][4];
    {
        const float* q0p = &g_qh[((size_t)h * N + row) * DK];
        const float* q8p = q0p + 8 * DK;
        #pragma unroll
        for (int ks = 0; ks < 2; ks++) {
            int d = ks * 16 + 2 * q;
            qa[ks][0] = packh2(q0p[d],     q0p[d + 1]);
            qa[ks][1] = packh2(q8p[d],     q8p[d + 1]);
            qa[ks][2] = packh2(q0p[d + 8], q0p[d + 9]);
            qa[ks][3] = packh2(q8p[d + 8], q8p[d + 9]);
        }
    }

    float o[4][4];
    #pragma unroll
    for (int n = 0; n < 4; n++)
        #pragma unroll
        for (int e = 0; e < 4; e++) o[n][e] = 0.f;

    float m0 = -INFINITY, m8 = -INFINITY, l0 = 0.f, l8 = 0.f;

    const int ck0 = (z * KSPAN) / 64;
    const int nch = KSPAN / 64;

    auto fill = [&](int buf, int ck) {
        const uint4* ks = (const uint4*)&g_kf[(size_t)(h * NCHUNK + ck) * 1024];
        const uint4* vs = (const uint4*)&g_vf[(size_t)(h * NCHUNK + ck) * 1024];
        #pragma unroll
        for (int i = 0; i < 2; i++) {
            int idx = i * 128 + tid;
            cp16((uint32_t)__cvta_generic_to_shared(&KBb[buf * 1024 + idx * 4]), ks + idx);
            cp16((uint32_t)__cvta_generic_to_shared(&VBb[buf * 1024 + idx * 4]), vs + idx);
        }
        const __half* bsrc = &g_bias[(size_t)q0 * N + ck * 64];
        __half* bdst = &BSb[buf * 64 * BSTR];
        #pragma unroll
        for (int i = 0; i < 4; i++) {
            int idx = i * 128 + tid;
            int r = idx >> 3, c8 = idx & 7;
            cp16((uint32_t)__cvta_generic_to_shared(&bdst[r * BSTR + c8 * 8]),
                 &bsrc[(size_t)r * N + c8 * 8]);
        }
    };

    fill(0, ck0);
    asm volatile("cp.async.commit_group;");

    for (int cc = 0; cc < nch; cc++) {
        const int cur = cc & 1;

        if (cc + 1 < nch) {
            fill(1 - cur, ck0 + cc + 1);
            asm volatile("cp.async.commit_group;");
            asm volatile("cp.async.wait_group 1;");
        } else {
            asm volatile("cp.async.wait_group 0;");
        }
        __syncthreads();

        const uint32_t* KBc = &KBb[cur * 1024];
        const uint32_t* VBc = &VBb[cur * 1024];
        const __half*   BSc = &BSb[cur * 64 * BSTR];

        float s[8][4];
        #pragma unroll
        for (int j = 0; j < 8; j++)
            #pragma unroll
            for (int e = 0; e < 4; e++) s[j][e] = 0.f;

        #pragma unroll
        for (int ks = 0; ks < 2; ks++) {
            #pragma unroll
            for (int j = 0; j < 8; j++) {
                uint2 b = *(const uint2*)&KBc[((ks * 8 + j) * 32 + lane) * 2];
                mma_f16(s[j][0], s[j][1], s[j][2], s[j][3],
                        qa[ks][0], qa[ks][1], qa[ks][2], qa[ks][3], b.x, b.y);
            }
        }

        {
            const __half* br0 = &BSc[(wr0 + g) * BSTR];
            const __half* br8 = br0 + 8 * BSTR;
            #pragma unroll
            for (int j = 0; j < 8; j++) {
                float2 b0 = __half22float2(*(const __half2*)&br0[8 * j + 2 * q]);
                float2 b8 = __half22float2(*(const __half2*)&br8[8 * j + 2 * q]);
                s[j][0] += b0.x; s[j][1] += b0.y;
                s[j][2] += b8.x; s[j][3] += b8.y;
            }
        }

        float mx0 = s[0][0], mx8 = s[0][2];
        #pragma unroll
        for (int j = 0; j < 8; j++) {
            mx0 = fmaxf(mx0, fmaxf(s[j][0], s[j][1]));
            mx8 = fmaxf(mx8, fmaxf(s[j][2], s[j][3]));
        }
        mx0 = fmaxf(mx0, __shfl_xor_sync(0xffffffffu, mx0, 1));
        mx0 = fmaxf(mx0, __shfl_xor_sync(0xffffffffu, mx0, 2));
        mx8 = fmaxf(mx8, __shfl_xor_sync(0xffffffffu, mx8, 1));
        mx8 = fmaxf(mx8, __shfl_xor_sync(0xffffffffu, mx8, 2));

        float mn0 = fmaxf(m0, mx0), mn8 = fmaxf(m8, mx8);
        float c0 = __expf(m0 - mn0), c8 = __expf(m8 - mn8);
        m0 = mn0; m8 = mn8;
        l0 *= c0;  l8 *= c8;
        #pragma unroll
        for (int n = 0; n < 4; n++) {
            o[n][0] *= c0; o[n][1] *= c0;
            o[n][2] *= c8; o[n][3] *= c8;
        }

        float p[8][4];
        #pragma unroll
        for (int j = 0; j < 8; j++) {
            p[j][0] = __expf(s[j][0] - m0);
            p[j][1] = __expf(s[j][1] - m0);
            p[j][2] = __expf(s[j][2] - m8);
            p[j][3] = __expf(s[j][3] - m8);
            l0 += p[j][0] + p[j][1];
            l8 += p[j][2] + p[j][3];
        }

        #pragma unroll
        for (int kk = 0; kk < 4; kk++) {
            uint32_t a0 = packh2(p[2 * kk][0],     p[2 * kk][1]);
            uint32_t a1 = packh2(p[2 * kk][2],     p[2 * kk][3]);
            uint32_t a2 = packh2(p[2 * kk + 1][0], p[2 * kk + 1][1]);
            uint32_t a3 = packh2(p[2 * kk + 1][2], p[2 * kk + 1][3]);
            #pragma unroll
            for (int n = 0; n < 4; n++) {
                uint2 b = *(const uint2*)&VBc[((kk * 4 + n) * 32 + lane) * 2];
                mma_f16(o[n][0], o[n][1], o[n][2], o[n][3], a0, a1, a2, a3, b.x, b.y);
            }
        }
        __syncthreads();
    }

    l0 += __shfl_xor_sync(0xffffffffu, l0, 1);
    l0 += __shfl_xor_sync(0xffffffffu, l0, 2);
    l8 += __shfl_xor_sync(0xffffffffu, l8, 1);
    l8 += __shfl_xor_sync(0xffffffffu, l8, 2);

    const int rid = (z * HEADS + h) * N + q0 + wr0 + g;
    if (q == 0) {
        g_pm[rid] = m0;     g_pl[rid] = l0;
        g_pm[rid + 8] = m8; g_pl[rid + 8] = l8;
    }
    float* pav0 = &g_pav[(size_t)rid * DK];
    float* pav8 = &g_pav[(size_t)(rid + 8) * DK];
    #pragma unroll
    for (int n = 0; n < 4; n++) {
        *(float2*)&pav0[8 * n + 2 * q] = make_float2(o[n][0], o[n][1]);
        *(float2*)&pav8[8 * n + 2 * q] = make_float2(o[n][2], o[n][3]);
    }
}

// -------------------- launch ------------------------------------------------
extern "C" void kernel_launch(void* const* d_in, const int* in_sizes, int n_in,
                              void* d_out, int out_size)
{
    const int*   label   = (const int*)  d_in[0];
    const float* dist    = (const float*)d_in[1];
    const float* contact = (const float*)d_in[2];
    const float* q       = (const float*)d_in[3];
    const float* k       = (const float*)d_in[4];
    const float* v       = (const float*)d_in[5];
    const float* Wq = (const float*)d_in[6];  const float* bq = (const float*)d_in[7];
    const float* Wk = (const float*)d_in[8];  const float* bk = (const float*)d_in[9];
    const float* Wv = (const float*)d_in[10]; const float* bv = (const float*)d_in[11];
    const float* Wo = (const float*)d_in[12]; const float* bo = (const float*)d_in[13];
    const float* Wd1 = (const float*)d_in[14]; const float* bd1 = (const float*)d_in[15];
    const float* Wd2 = (const float*)d_in[16]; const float* bd2 = (const float*)d_in[17];
    const float* Wc1 = (const float*)d_in[18]; const float* bc1 = (const float*)d_in[19];
    const float* Wc2 = (const float*)d_in[20]; const float* bc2 = (const float*)d_in[21];
    float* out = (float*)d_out;

    float* p_qh;
    cudaGetSymbolAddress((void**)&p_qh, g_qh);

    bias_kernel<<<(N * N / 4) / 256, 256>>>(label, dist, contact,
                                            Wd1, bd1, Wd2, bd2, Wc1, bc1, Wc2, bc2);

    const float scale = 1.f / sqrtf((float)DK);
    qkv_proj<<<dim3(N / 64, HIDDEN / 64, 3), 256>>>(q, k, v, Wq, Wk, Wv,
                                                    bq, bk, bv, p_qh, scale);

    const int attn_smem = 4096 * 4 + 2 * 64 * BSTR * 2;   // 34816 B
    static int smem_set = 0;
    if (!smem_set) {
        cudaFuncSetAttribute(attn_mma_kernel,
                             cudaFuncAttributeMaxDynamicSharedMemorySize, attn_smem);
        smem_set = 1;
    }
    attn_mma_kernel<<<dim3(N / 64, HEADS, NSPLIT), 128, attn_smem>>>();

    o_proj_fused<<<dim3(N / 64, HIDDEN / 64), 256>>>(Wo, bo, out);
}

// round 14
// speedup vs baseline: 1.2497x; 1.0527x over previous
#include <cuda_runtime.h>
#include <cuda_fp16.h>
#include <math.h>
#include <stdint.h>

#define N 2048
#define HIDDEN 256
#define HEADS 8
#define DK 32
#define NSPLIT 2
#define KSPAN (N / NSPLIT)
#define NCHUNK (N / 64)
#define BSTR 72   // bias smem row stride in halves

#define PROJ_BLOCKS (32 * 4 * 3)          // 384
#define BIAS_BLOCKS ((N * N / 4) / 256)   // 4096

// -------------------- scratch (__device__ globals; no allocs allowed) -----
__device__ __half g_bias[N * N];                   // 8 MB fp16 pair bias
__device__ float g_qh[HEADS * N * DK];             // head-major projected q (scaled)
__device__ uint32_t g_kf[HEADS * NCHUNK * 1024];   // fragment-major fp16 K
__device__ uint32_t g_vf[HEADS * NCHUNK * 1024];   // fragment-major fp16 V
// split-K partials (NSPLIT=2 -> 4 MB)
__device__ float g_pm[NSPLIT * HEADS * N];
__device__ float g_pl[NSPLIT * HEADS * N];
__device__ float g_pav[NSPLIT * HEADS * N * DK];

// -------------------- helpers ---------------------------------------------
__device__ __forceinline__ uint32_t f2tf(float f) {
    uint32_t u;
    asm("cvt.rna.tf32.f32 %0, %1;" : "=r"(u) : "f"(f));
    return u;
}

__device__ __forceinline__ uint32_t packh2(float lo, float hi) {
    __half2 h = __floats2half2_rn(lo, hi);
    return *reinterpret_cast<uint32_t*>(&h);
}

__device__ __forceinline__ void mma_tf32(float& d0, float& d1, float& d2, float& d3,
                                         uint32_t a0, uint32_t a1, uint32_t a2, uint32_t a3,
                                         uint32_t b0, uint32_t b1)
{
    asm volatile("mma.sync.aligned.m16n8k8.row.col.f32.tf32.tf32.f32 "
                 "{%0,%1,%2,%3}, {%4,%5,%6,%7}, {%8,%9}, {%0,%1,%2,%3};"
                 : "+f"(d0), "+f"(d1), "+f"(d2), "+f"(d3)
                 : "r"(a0), "r"(a1), "r"(a2), "r"(a3), "r"(b0), "r"(b1));
}

__device__ __forceinline__ void mma_f16(float& d0, float& d1, float& d2, float& d3,
                                        uint32_t a0, uint32_t a1, uint32_t a2, uint32_t a3,
                                        uint32_t b0, uint32_t b1)
{
    asm volatile("mma.sync.aligned.m16n8k16.row.col.f32.f16.f16.f32 "
                 "{%0,%1,%2,%3}, {%4,%5,%6,%7}, {%8,%9}, {%0,%1,%2,%3};"
                 : "+f"(d0), "+f"(d1), "+f"(d2), "+f"(d3)
                 : "r"(a0), "r"(a1), "r"(a2), "r"(a3), "r"(b0), "r"(b1));
}

__device__ __forceinline__ void cp16(uint32_t smem_dst, const void* gsrc) {
    asm volatile("cp.async.cg.shared.global [%0], [%1], 16;"
                 :: "r"(smem_dst), "l"(gsrc));
}

// K fragment word index (fp16x2 packed over d-pairs): B-frag of m16n8k16
__device__ __forceinline__ int kaddr16(int key, int d) {
    return ((d >> 4) * 8 + (key >> 3)) * 64 + ((key & 7) * 4 + ((d & 7) >> 1)) * 2 + ((d >> 3) & 1);
}
// V fragment half index (fp16x2 packed over key-pairs)
__device__ __forceinline__ int vaddr16h(int key, int d) {
    return ((((key >> 4) * 4 + (d >> 3)) * 32 + (d & 7) * 4 + ((key & 7) >> 1)) * 2
            + ((key >> 3) & 1)) * 2 + (key & 1);
}

// -------------------- tf32 projection GEMM body ----------------------------
// mode 0: head-major scaled (Q)   mode 2: K fp16 fragment-major
// mode 3: V fp16 fragment-major
__device__ __forceinline__ void proj_body(const float* __restrict__ A,
                                          const float* __restrict__ W,
                                          const float* __restrict__ bias,
                                          float* __restrict__ out,
                                          float scale, int mode, int m0, int n0)
{
    __shared__ uint4 AF[2][16 * 32];
    __shared__ uint2 BF[2][32 * 32];

    const int t    = threadIdx.x;
    const int lane = t & 31;
    const int w    = t >> 5;
    const int q    = lane & 3;
    const int g    = lane >> 2;
    const int mf    = w >> 1;
    const int nhalf = w & 1;

    float acc[4][4];
    #pragma unroll
    for (int j = 0; j < 4; j++)
        #pragma unroll
        for (int e = 0; e < 4; e++) acc[j][e] = 0.f;

    const int a_m0 = t >> 3,         a_k4_0 = t & 7;
    const int a_m1 = (t + 256) >> 3, a_k4_1 = (t + 256) & 7;
    const int b_k0 = t >> 4,         b_n4_0 = t & 15;
    const int b_k1 = (t + 256) >> 4, b_n4_1 = (t + 256) & 15;

    float4 ra0, ra1, rb0, rb1;
    ra0 = *(const float4*)&A[(size_t)(m0 + a_m0) * 256 + 0 + a_k4_0 * 4];
    ra1 = *(const float4*)&A[(size_t)(m0 + a_m1) * 256 + 0 + a_k4_1 * 4];
    rb0 = *(const float4*)&W[(size_t)(0 + b_k0) * 256 + n0 + b_n4_0 * 4];
    rb1 = *(const float4*)&W[(size_t)(0 + b_k1) * 256 + n0 + b_n4_1 * 4];

    for (int c = 0; c < 8; c++) {
        const int buf = c & 1;
        {
            #pragma unroll
            for (int p = 0; p < 2; p++) {
                int m  = p ? a_m1 : a_m0;
                int k4 = p ? a_k4_1 : a_k4_0;
                float4 v = p ? ra1 : ra0;
                int frag = (m >> 4) * 4 + (k4 >> 1);
                int idx  = (k4 & 1) * 2 + ((m & 15) >> 3);
                uint32_t* dst = (uint32_t*)&AF[buf][frag * 32 + ((m & 7) * 4)];
                dst[0 * 4 + idx] = f2tf(v.x);
                dst[1 * 4 + idx] = f2tf(v.y);
                dst[2 * 4 + idx] = f2tf(v.z);
                dst[3 * 4 + idx] = f2tf(v.w);
            }
            #pragma unroll
            for (int p = 0; p < 2; p++) {
                int k  = p ? b_k1 : b_k0;
                int n4 = p ? b_n4_1 : b_n4_0;
                float4 v = p ? rb1 : rb0;
                int frag = (n4 >> 1) * 4 + (k >> 3);
                int hi   = (k >> 2) & 1;
                uint32_t* dst = (uint32_t*)&BF[buf][frag * 32 + (n4 & 1) * 16 + (k & 3)];
                dst[0 * 8 + hi] = f2tf(v.x);
                dst[1 * 8 + hi] = f2tf(v.y);
                dst[2 * 8 + hi] = f2tf(v.z);
                dst[3 * 8 + hi] = f2tf(v.w);
            }
        }
        __syncthreads();

        if (c < 7) {
            int kt = (c + 1) * 32;
            ra0 = *(const float4*)&A[(size_t)(m0 + a_m0) * 256 + kt + a_k4_0 * 4];
            ra1 = *(const float4*)&A[(size_t)(m0 + a_m1) * 256 + kt + a_k4_1 * 4];
            rb0 = *(const float4*)&W[(size_t)(kt + b_k0) * 256 + n0 + b_n4_0 * 4];
            rb1 = *(const float4*)&W[(size_t)(kt + b_k1) * 256 + n0 + b_n4_1 * 4];
        }

        #pragma unroll
        for (int ks = 0; ks < 4; ks++) {
            uint4 a = AF[buf][(mf * 4 + ks) * 32 + lane];
            #pragma unroll
            for (int j = 0; j < 4; j++) {
                uint2 b = BF[buf][((nhalf * 4 + j) * 4 + ks) * 32 + lane];
                mma_tf32(acc[j][0], acc[j][1], acc[j][2], acc[j][3],
                         a.x, a.y, a.z, a.w, b.x, b.y);
            }
        }
    }

    const int row0 = m0 + mf * 16 + g;
    const int key0 = mf * 16 + g;
    const int ck   = m0 >> 6;
    #pragma unroll
    for (int j = 0; j < 4; j++) {
        int col = n0 + nhalf * 32 + j * 8 + 2 * q;
        float2 bz = *(const float2*)&bias[col];
        float v00 = acc[j][0] + bz.x, v01 = acc[j][1] + bz.y;
        float v10 = acc[j][2] + bz.x, v11 = acc[j][3] + bz.y;
        if (mode == 0) {
            v00 *= scale; v01 *= scale; v10 *= scale; v11 *= scale;
            size_t base = (size_t)(col >> 5) * ((size_t)N * 32) + (col & 31);
            *(float2*)&out[base + (size_t)row0 * 32]       = make_float2(v00, v01);
            *(float2*)&out[base + (size_t)(row0 + 8) * 32] = make_float2(v10, v11);
        } else {
            int hh = col >> 5, dd = col & 31;
            if (mode == 2) {
                uint32_t* KD = &g_kf[((size_t)hh * NCHUNK + ck) * 1024];
                KD[kaddr16(key0,     dd)] = packh2(v00, v01);
                KD[kaddr16(key0 + 8, dd)] = packh2(v10, v11);
            } else {
                __half* VD = (__half*)&g_vf[((size_t)hh * NCHUNK + ck) * 1024];
                VD[vaddr16h(key0,     dd)]     = __float2half_rn(v00);
                VD[vaddr16h(key0,     dd + 1)] = __float2half_rn(v01);
                VD[vaddr16h(key0 + 8, dd)]     = __float2half_rn(v10);
                VD[vaddr16h(key0 + 8, dd + 1)] = __float2half_rn(v11);
            }
        }
    }
}

// -------------------- fused prep: QKV projections + pair-bias --------------
// grid = PROJ_BLOCKS + BIAS_BLOCKS 1-D blocks of 256 threads.
// Blocks [0,384): tf32 Q/K/V projection tiles (tensor/latency-bound).
// Blocks [384, 4480): fp16 bias stream (DRAM-bound) — backfills idle slots.
__global__ __launch_bounds__(256) void prep_kernel(
    const float* __restrict__ q, const float* __restrict__ k, const float* __restrict__ v,
    const float* __restrict__ Wq, const float* __restrict__ Wk, const float* __restrict__ Wv,
    const float* __restrict__ bq, const float* __restrict__ bk, const float* __restrict__ bv,
    float* __restrict__ oq, float scale,
    const int* __restrict__ label, const float* __restrict__ dist,
    const float* __restrict__ contact,
    const float* __restrict__ Wd1, const float* __restrict__ bd1,
    const float* __restrict__ Wd2, const float* __restrict__ bd2,
    const float* __restrict__ Wc1, const float* __restrict__ bc1,
    const float* __restrict__ Wc2, const float* __restrict__ bc2)
{
    const int bid = blockIdx.x;
    if (bid < PROJ_BLOCKS) {
        const int pz  = bid >> 7;          // 0..2
        const int rem = bid & 127;
        const int m0  = (rem & 31) * 64;
        const int n0  = (rem >> 5) * 64;
        if (pz == 0)      proj_body(q, Wq, bq, oq,      scale, 0, m0, n0);
        else if (pz == 1) proj_body(k, Wk, bk, nullptr, 1.f,   2, m0, n0);
        else              proj_body(v, Wv, bv, nullptr, 1.f,   3, m0, n0);
        return;
    }

    // ---- bias path ----
    __shared__ float4 cf;
    if (threadIdx.x == 0) {
        float am = 0.f, al = 0.f, c0 = bd2[0] + bc2[0], cm = 0.f;
        #pragma unroll
        for (int h = 0; h < 16; h++) {
            am += Wd1[h]      * Wd2[h];
            al += Wd1[16 + h] * Wd2[h];
            c0 += bd1[h]      * Wd2[h];
            cm += Wc1[h]      * Wc2[h];
            al += Wc1[16 + h] * Wc2[h];
            c0 += bc1[h]      * Wc2[h];
        }
        cf = make_float4(am, cm, al, c0);
    }
    __syncthreads();
    const float am = cf.x, cm = cf.y, al = cf.z, c0 = cf.w;

    int i = (bid - PROJ_BLOCKS) * 256 + threadIdx.x;   // float4 index
    float4 dm = ((const float4*)dist)[i];
    float4 cv = ((const float4*)contact)[i];
    int4   lb = ((const int4*)label)[i];
    float ox = fmaf(am, dm.x, fmaf(cm, cv.x, fmaf(al, (float)lb.x, c0)));
    float oy = fmaf(am, dm.y, fmaf(cm, cv.y, fmaf(al, (float)lb.y, c0)));
    float oz = fmaf(am, dm.z, fmaf(cm, cv.z, fmaf(al, (float)lb.z, c0)));
    float ow = fmaf(am, dm.w, fmaf(cm, cv.w, fmaf(al, (float)lb.w, c0)));
    uint2 r;
    r.x = packh2(ox, oy);
    r.y = packh2(oz, ow);
    ((uint2*)g_bias)[i] = r;
}

// -------------------- O-projection with fused 2-way split-K combine --------
__global__ __launch_bounds__(256) void o_proj_fused(const float* __restrict__ W,
                                                    const float* __restrict__ bo,
                                                    float* __restrict__ out)
{
    __shared__ uint4 AF[2][16 * 32];
    __shared__ uint2 BF[2][32 * 32];
    __shared__ float2 WC[64][8];       // [row_local][head] = (w0/l, w1/l)

    const int t    = threadIdx.x;
    const int lane = t & 31;
    const int w    = t >> 5;
    const int q    = lane & 3;
    const int g    = lane >> 2;
    const int m0   = blockIdx.x * 64;
    const int n0   = blockIdx.y * 64;
    const int mf    = w >> 1;
    const int nhalf = w & 1;

    #pragma unroll
    for (int p = 0; p < 2; p++) {
        int idx = t + p * 256;
        int r = idx >> 3, hh = idx & 7;
        int row = m0 + r;
        float pm0 = g_pm[(0 * HEADS + hh) * N + row];
        float pm1 = g_pm[(1 * HEADS + hh) * N + row];
        float pl0 = g_pl[(0 * HEADS + hh) * N + row];
        float pl1 = g_pl[(1 * HEADS + hh) * N + row];
        float M = fmaxf(pm0, pm1);
        float w0 = __expf(pm0 - M), w1 = __expf(pm1 - M);
        float inv = 1.f / (pl0 * w0 + pl1 * w1);
        WC[r][hh] = make_float2(w0 * inv, w1 * inv);
    }
    __syncthreads();

    float acc[4][4];
    #pragma unroll
    for (int j = 0; j < 4; j++)
        #pragma unroll
        for (int e = 0; e < 4; e++) acc[j][e] = 0.f;

    const int a_m0 = t >> 3,         a_k4_0 = t & 7;
    const int a_m1 = (t + 256) >> 3, a_k4_1 = (t + 256) & 7;
    const int b_k0 = t >> 4,         b_n4_0 = t & 15;
    const int b_k1 = (t + 256) >> 4, b_n4_1 = (t + 256) & 15;

    float4 pv[2][2];
    float4 rb0, rb1;
    #pragma unroll
    for (int p = 0; p < 2; p++) {
        int m  = p ? a_m1 : a_m0;
        int d0 = (p ? a_k4_1 : a_k4_0) * 4;
        #pragma unroll
        for (int s = 0; s < NSPLIT; s++)
            pv[p][s] = *(const float4*)&g_pav[(((size_t)(s * HEADS + 0)) * N + m0 + m) * DK + d0];
    }
    rb0 = *(const float4*)&W[(size_t)(0 + b_k0) * 256 + n0 + b_n4_0 * 4];
    rb1 = *(const float4*)&W[(size_t)(0 + b_k1) * 256 + n0 + b_n4_1 * 4];

    for (int c = 0; c < 8; c++) {
        const int buf = c & 1;
        {
            #pragma unroll
            for (int p = 0; p < 2; p++) {
                int m  = p ? a_m1 : a_m0;
                int k4 = p ? a_k4_1 : a_k4_0;
                float2 wc = WC[m][c];
                float4 v;
                v.x = wc.x * pv[p][0].x + wc.y * pv[p][1].x;
                v.y = wc.x * pv[p][0].y + wc.y * pv[p][1].y;
                v.z = wc.x * pv[p][0].z + wc.y * pv[p][1].z;
                v.w = wc.x * pv[p][0].w + wc.y * pv[p][1].w;
                int frag = (m >> 4) * 4 + (k4 >> 1);
                int idx  = (k4 & 1) * 2 + ((m & 15) >> 3);
                uint32_t* dst = (uint32_t*)&AF[buf][frag * 32 + ((m & 7) * 4)];
                dst[0 * 4 + idx] = f2tf(v.x);
                dst[1 * 4 + idx] = f2tf(v.y);
                dst[2 * 4 + idx] = f2tf(v.z);
                dst[3 * 4 + idx] = f2tf(v.w);
            }
            #pragma unroll
            for (int p = 0; p < 2; p++) {
                int k  = p ? b_k1 : b_k0;
                int n4 = p ? b_n4_1 : b_n4_0;
                float4 v = p ? rb1 : rb0;
                int frag = (n4 >> 1) * 4 + (k >> 3);
                int hi   = (k >> 2) & 1;
                uint32_t* dst = (uint32_t*)&BF[buf][frag * 32 + (n4 & 1) * 16 + (k & 3)];
                dst[0 * 8 + hi] = f2tf(v.x);
                dst[1 * 8 + hi] = f2tf(v.y);
                dst[2 * 8 + hi] = f2tf(v.z);
                dst[3 * 8 + hi] = f2tf(v.w);
            }
        }
        __syncthreads();

        if (c < 7) {
            int hh = c + 1;
            #pragma unroll
            for (int p = 0; p < 2; p++) {
                int m  = p ? a_m1 : a_m0;
                int d0 = (p ? a_k4_1 : a_k4_0) * 4;
                #pragma unroll
                for (int s = 0; s < NSPLIT; s++)
                    pv[p][s] = *(const float4*)&g_pav[(((size_t)(s * HEADS + hh)) * N + m0 + m) * DK + d0];
            }
            int kt = hh * 32;
            rb0 = *(const float4*)&W[(size_t)(kt + b_k0) * 256 + n0 + b_n4_0 * 4];
            rb1 = *(const float4*)&W[(size_t)(kt + b_k1) * 256 + n0 + b_n4_1 * 4];
        }

        #pragma unroll
        for (int ks = 0; ks < 4; ks++) {
            uint4 a = AF[buf][(mf * 4 + ks) * 32 + lane];
            #pragma unroll
            for (int j = 0; j < 4; j++) {
                uint2 b = BF[buf][((nhalf * 4 + j) * 4 + ks) * 32 + lane];
                mma_tf32(acc[j][0], acc[j][1], acc[j][2], acc[j][3],
                         a.x, a.y, a.z, a.w, b.x, b.y);
            }
        }
    }

    const int row0 = m0 + mf * 16 + g;
    #pragma unroll
    for (int j = 0; j < 4; j++) {
        int col = n0 + nhalf * 32 + j * 8 + 2 * q;
        float2 bz = *(const float2*)&bo[col];
        *(float2*)&out[(size_t)row0 * 256 + col] =
            make_float2(acc[j][0] + bz.x, acc[j][1] + bz.y);
        *(float2*)&out[(size_t)(row0 + 8) * 256 + col] =
            make_float2(acc[j][2] + bz.x, acc[j][3] + bz.y);
    }
}

// -------------------- fp16 flash attention (R9 shape, NSPLIT=2) ------------
__global__ __launch_bounds__(128) void attn_mma_kernel()
{
    extern __shared__ uint32_t dsm[];
    uint32_t* KBb = dsm;                     // [2][1024]
    uint32_t* VBb = dsm + 2048;              // [2][1024]
    __half*   BSb = (__half*)(dsm + 4096);   // [2][64*BSTR]

    const int tid  = threadIdx.x;
    const int lane = tid & 31;
    const int warp = tid >> 5;
    const int q    = lane & 3;
    const int g    = lane >> 2;
    const int h  = blockIdx.y;
    const int z  = blockIdx.z;
    const int q0 = blockIdx.x * 64;
    const int wr0 = warp * 16;
    const int row = q0 + wr0 + g;

    uint32_t qa[2][4];
    {
        const float* q0p = &g_qh[((size_t)h * N + row) * DK];
        const float* q8p = q0p + 8 * DK;
        #pragma unroll
        for (int ks = 0; ks < 2; ks++) {
            int d = ks * 16 + 2 * q;
            qa[ks][0] = packh2(q0p[d],     q0p[d + 1]);
            qa[ks][1] = packh2(q8p[d],     q8p[d + 1]);
            qa[ks][2] = packh2(q0p[d + 8], q0p[d + 9]);
            qa[ks][3] = packh2(q8p[d + 8], q8p[d + 9]);
        }
    }

    float o[4][4];
    #pragma unroll
    for (int n = 0; n < 4; n++)
        #pragma unroll
        for (int e = 0; e < 4; e++) o[n][e] = 0.f;

    float m0 = -INFINITY, m8 = -INFINITY, l0 = 0.f, l8 = 0.f;

    const int ck0 = (z * KSPAN) / 64;
    const int nch = KSPAN / 64;

    auto fill = [&](int buf, int ck) {
        const uint4* ks = (const uint4*)&g_kf[(size_t)(h * NCHUNK + ck) * 1024];
        const uint4* vs = (const uint4*)&g_vf[(size_t)(h * NCHUNK + ck) * 1024];
        #pragma unroll
        for (int i = 0; i < 2; i++) {
            int idx = i * 128 + tid;
            cp16((uint32_t)__cvta_generic_to_shared(&KBb[buf * 1024 + idx * 4]), ks + idx);
            cp16((uint32_t)__cvta_generic_to_shared(&VBb[buf * 1024 + idx * 4]), vs + idx);
        }
        const __half* bsrc = &g_bias[(size_t)q0 * N + ck * 64];
        __half* bdst = &BSb[buf * 64 * BSTR];
        #pragma unroll
        for (int i = 0; i < 4; i++) {
            int idx = i * 128 + tid;
            int r = idx >> 3, c8 = idx & 7;
            cp16((uint32_t)__cvta_generic_to_shared(&bdst[r * BSTR + c8 * 8]),
                 &bsrc[(size_t)r * N + c8 * 8]);
        }
    };

    fill(0, ck0);
    asm volatile("cp.async.commit_group;");

    for (int cc = 0; cc < nch; cc++) {
        const int cur = cc & 1;

        if (cc + 1 < nch) {
            fill(1 - cur, ck0 + cc + 1);
            asm volatile("cp.async.commit_group;");
            asm volatile("cp.async.wait_group 1;");
        } else {
            asm volatile("cp.async.wait_group 0;");
        }
        __syncthreads();

        const uint32_t* KBc = &KBb[cur * 1024];
        const uint32_t* VBc = &VBb[cur * 1024];
        const __half*   BSc = &BSb[cur * 64 * BSTR];

        float s[8][4];
        #pragma unroll
        for (int j = 0; j < 8; j++)
            #pragma unroll
            for (int e = 0; e < 4; e++) s[j][e] = 0.f;

        #pragma unroll
        for (int ks = 0; ks < 2; ks++) {
            #pragma unroll
            for (int j = 0; j < 8; j++) {
                uint2 b = *(const uint2*)&KBc[((ks * 8 + j) * 32 + lane) * 2];
                mma_f16(s[j][0], s[j][1], s[j][2], s[j][3],
                        qa[ks][0], qa[ks][1], qa[ks][2], qa[ks][3], b.x, b.y);
            }
        }

        {
            const __half* br0 = &BSc[(wr0 + g) * BSTR];
            const __half* br8 = br0 + 8 * BSTR;
            #pragma unroll
            for (int j = 0; j < 8; j++) {
                float2 b0 = __half22float2(*(const __half2*)&br0[8 * j + 2 * q]);
                float2 b8 = __half22float2(*(const __half2*)&br8[8 * j + 2 * q]);
                s[j][0] += b0.x; s[j][1] += b0.y;
                s[j][2] += b8.x; s[j][3] += b8.y;
            }
        }

        float mx0 = s[0][0], mx8 = s[0][2];
        #pragma unroll
        for (int j = 0; j < 8; j++) {
            mx0 = fmaxf(mx0, fmaxf(s[j][0], s[j][1]));
            mx8 = fmaxf(mx8, fmaxf(s[j][2], s[j][3]));
        }
        mx0 = fmaxf(mx0, __shfl_xor_sync(0xffffffffu, mx0, 1));
        mx0 = fmaxf(mx0, __shfl_xor_sync(0xffffffffu, mx0, 2));
        mx8 = fmaxf(mx8, __shfl_xor_sync(0xffffffffu, mx8, 1));
        mx8 = fmaxf(mx8, __shfl_xor_sync(0xffffffffu, mx8, 2));

        float mn0 = fmaxf(m0, mx0), mn8 = fmaxf(m8, mx8);
        float c0 = __expf(m0 - mn0), c8 = __expf(m8 - mn8);
        m0 = mn0; m8 = mn8;
        l0 *= c0;  l8 *= c8;
        #pragma unroll
        for (int n = 0; n < 4; n++) {
            o[n][0] *= c0; o[n][1] *= c0;
            o[n][2] *= c8; o[n][3] *= c8;
        }

        float p[8][4];
        #pragma unroll
        for (int j = 0; j < 8; j++) {
            p[j][0] = __expf(s[j][0] - m0);
            p[j][1] = __expf(s[j][1] - m0);
            p[j][2] = __expf(s[j][2] - m8);
            p[j][3] = __expf(s[j][3] - m8);
            l0 += p[j][0] + p[j][1];
            l8 += p[j][2] + p[j][3];
        }

        #pragma unroll
        for (int kk = 0; kk < 4; kk++) {
            uint32_t a0 = packh2(p[2 * kk][0],     p[2 * kk][1]);
            uint32_t a1 = packh2(p[2 * kk][2],     p[2 * kk][3]);
            uint32_t a2 = packh2(p[2 * kk + 1][0], p[2 * kk + 1][1]);
            uint32_t a3 = packh2(p[2 * kk + 1][2], p[2 * kk + 1][3]);
            #pragma unroll
            for (int n = 0; n < 4; n++) {
                uint2 b = *(const uint2*)&VBc[((kk * 4 + n) * 32 + lane) * 2];
                mma_f16(o[n][0], o[n][1], o[n][2], o[n][3], a0, a1, a2, a3, b.x, b.y);
            }
        }
        __syncthreads();
    }

    l0 += __shfl_xor_sync(0xffffffffu, l0, 1);
    l0 += __shfl_xor_sync(0xffffffffu, l0, 2);
    l8 += __shfl_xor_sync(0xffffffffu, l8, 1);
    l8 += __shfl_xor_sync(0xffffffffu, l8, 2);

    const int rid = (z * HEADS + h) * N + q0 + wr0 + g;
    if (q == 0) {
        g_pm[rid] = m0;     g_pl[rid] = l0;
        g_pm[rid + 8] = m8; g_pl[rid + 8] = l8;
    }
    float* pav0 = &g_pav[(size_t)rid * DK];
    float* pav8 = &g_pav[(size_t)(rid + 8) * DK];
    #pragma unroll
    for (int n = 0; n < 4; n++) {
        *(float2*)&pav0[8 * n + 2 * q] = make_float2(o[n][0], o[n][1]);
        *(float2*)&pav8[8 * n + 2 * q] = make_float2(o[n][2], o[n][3]);
    }
}

// -------------------- launch ------------------------------------------------
extern "C" void kernel_launch(void* const* d_in, const int* in_sizes, int n_in,
                              void* d_out, int out_size)
{
    const int*   label   = (const int*)  d_in[0];
    const float* dist    = (const float*)d_in[1];
    const float* contact = (const float*)d_in[2];
    const float* q       = (const float*)d_in[3];
    const float* k       = (const float*)d_in[4];
    const float* v       = (const float*)d_in[5];
    const float* Wq = (const float*)d_in[6];  const float* bq = (const float*)d_in[7];
    const float* Wk = (const float*)d_in[8];  const float* bk = (const float*)d_in[9];
    const float* Wv = (const float*)d_in[10]; const float* bv = (const float*)d_in[11];
    const float* Wo = (const float*)d_in[12]; const float* bo = (const float*)d_in[13];
    const float* Wd1 = (const float*)d_in[14]; const float* bd1 = (const float*)d_in[15];
    const float* Wd2 = (const float*)d_in[16]; const float* bd2 = (const float*)d_in[17];
    const float* Wc1 = (const float*)d_in[18]; const float* bc1 = (const float*)d_in[19];
    const float* Wc2 = (const float*)d_in[20]; const float* bc2 = (const float*)d_in[21];
    float* out = (float*)d_out;

    float* p_qh;
    cudaGetSymbolAddress((void**)&p_qh, g_qh);

    const float scale = 1.f / sqrtf((float)DK);
    prep_kernel<<<PROJ_BLOCKS + BIAS_BLOCKS, 256>>>(
        q, k, v, Wq, Wk, Wv, bq, bk, bv, p_qh, scale,
        label, dist, contact, Wd1, bd1, Wd2, bd2, Wc1, bc1, Wc2, bc2);

    const int attn_smem = 4096 * 4 + 2 * 64 * BSTR * 2;   // 34816 B
    static int smem_set = 0;
    if (!smem_set) {
        cudaFuncSetAttribute(attn_mma_kernel,
                             cudaFuncAttributeMaxDynamicSharedMemorySize, attn_smem);
        smem_set = 1;
    }
    attn_mma_kernel<<<dim3(N / 64, HEADS, NSPLIT), 128, attn_smem>>>();

    o_proj_fused<<<dim3(N / 64, HIDDEN / 64), 256>>>(Wo, bo, out);
}